// round 12
// baseline (speedup 1.0000x reference)
#include <cuda_runtime.h>
#include <cuda_bf16.h>
#include <math.h>
#include <stdint.h>

// Problem constants
#define S_LEN 1024
#define BATCH 4
#define DMODEL 1024
#define NHEAD 16
#define HDIM 64
#define M4 4096          // BATCH * S_LEN
#define DFF 4096
#define NREL 101         // 2*MAXREL+1

// ---------------- scratch (device globals; no allocations allowed) ----------
__device__ float g_hn  [M4 * DMODEL];          // rmsnorm(x), full fp32 (residual)
__device__ float g_hnr [M4 * DMODEL];          // rmsnorm(x), tf32-rounded (GEMM A)
__device__ float g_q   [M4 * DMODEL];          // tf32-rounded
__device__ float g_k   [M4 * DMODEL];          // tf32-rounded
__device__ float g_v   [M4 * DMODEL];          // tf32-rounded
__device__ float g_qrel[64 * 1024 * NREL];     // [bh, q, r]
__device__ float g_o   [M4 * DMODEL];          // attn head outputs, tf32-rounded
__device__ float g_h2  [M4 * DMODEL];          // h + attn_out, full fp32
__device__ float g_ffin[M4 * DMODEL];          // rmsnorm(h2), tf32-rounded
__device__ float g_gelu[(size_t)M4 * DFF];     // gelu(...), tf32-rounded
__device__ float g_wr  [12 * 1024 * 1024];     // tf32-rounded weights
#define WOFF_Q   0
#define WOFF_K   (1024*1024)
#define WOFF_V   (2*1024*1024)
#define WOFF_O   (3*1024*1024)
#define WOFF_IN  (4*1024*1024)
#define WOFF_OUT (8*1024*1024)

// ---------------- helpers ----------------------------------------------------
__device__ __forceinline__ float gelu_f(float x) {
    return 0.5f * x * (1.0f + erff(x * 0.70710678118654752f));
}

__device__ __forceinline__ uint32_t f2tf(float f) {
    uint32_t u;
    asm("cvt.rna.tf32.f32 %0, %1;" : "=r"(u) : "f"(f));
    return u;
}
__device__ __forceinline__ float rnd_tf(float f) {
    return __uint_as_float(f2tf(f));
}

// D = A(16x8, row) * B(8x8, col) + D   (tf32 inputs, f32 accum)
__device__ __forceinline__ void mma8(float* c, const uint32_t* a, const uint32_t* b) {
    asm volatile(
        "mma.sync.aligned.m16n8k8.row.col.f32.tf32.tf32.f32 "
        "{%0,%1,%2,%3}, {%4,%5,%6,%7}, {%8,%9}, {%0,%1,%2,%3};"
        : "+f"(c[0]), "+f"(c[1]), "+f"(c[2]), "+f"(c[3])
        : "r"(a[0]), "r"(a[1]), "r"(a[2]), "r"(a[3]), "r"(b[0]), "r"(b[1]));
}

// ldmatrix x4 over fp32 data: each 8x8 b16 matrix == 8 rows x 4 fp32 cols;
// thread lane r*4+c receives fp32 element [row r][col c] -> tf32 frag layout.
__device__ __forceinline__ void ldsm4(uint32_t& r0, uint32_t& r1,
                                      uint32_t& r2, uint32_t& r3, uint32_t addr) {
    asm volatile("ldmatrix.sync.aligned.m8n8.x4.shared.b16 {%0,%1,%2,%3}, [%4];"
                 : "=r"(r0), "=r"(r1), "=r"(r2), "=r"(r3) : "r"(addr));
}

__device__ __forceinline__ void cpa16(uint32_t smem, const void* gmem) {
    asm volatile("cp.async.cg.shared.global [%0], [%1], 16;\n"
                 :: "r"(smem), "l"(gmem));
}
__device__ __forceinline__ void cpa_commit() {
    asm volatile("cp.async.commit_group;\n");
}
template <int N>
__device__ __forceinline__ void cpa_wait() {
    asm volatile("cp.async.wait_group %0;\n" :: "n"(N));
}

// 256-thread block reduce (8 warps). domax: true -> max, false -> sum.
__device__ __forceinline__ float blk_reduce(float v, float* red, bool domax) {
    #pragma unroll
    for (int o = 16; o > 0; o >>= 1) {
        float u = __shfl_xor_sync(0xffffffffu, v, o);
        v = domax ? fmaxf(v, u) : (v + u);
    }
    __syncthreads();
    if ((threadIdx.x & 31) == 0) red[threadIdx.x >> 5] = v;
    __syncthreads();
    float t = red[0];
    #pragma unroll
    for (int i = 1; i < 8; i++) t = domax ? fmaxf(t, red[i]) : (t + red[i]);
    return t;
}

// ---------------- tf32 pre-rounding (weights) ---------------------------------
__global__ void __launch_bounds__(256)
round_tf32_kernel(const float4* __restrict__ in, float4* __restrict__ out, int n4) {
    int i = blockIdx.x * 256 + threadIdx.x;
    if (i < n4) {
        float4 v = in[i];
        out[i] = make_float4(rnd_tf(v.x), rnd_tf(v.y), rnd_tf(v.z), rnd_tf(v.w));
    }
}

// ---------------- RMSNorm -----------------------------------------------------
// out_full (may be null): full fp32; out_r: tf32-rounded copy for GEMM input.
__global__ void __launch_bounds__(256)
rmsnorm_kernel(const float* __restrict__ in, const float* __restrict__ g,
               float* __restrict__ out_full, float* __restrict__ out_r,
               int transpose_in) {
    __shared__ float red[8];
    int row = blockIdx.x;
    int tid = threadIdx.x;
    const float* xr = in + (size_t)row * DMODEL;
    float4 v = *(const float4*)&xr[tid * 4];
    float ss = v.x * v.x + v.y * v.y + v.z * v.z + v.w * v.w;
    ss = blk_reduce(ss, red, false);
    float rms = sqrtf(ss) * 0.03125f;                // /sqrt(1024)
    float inv = 1.0f / (rms + 1e-8f);
    float4 gv = *(const float4*)&g[tid * 4];
    float4 o = make_float4(v.x * inv * gv.x, v.y * inv * gv.y,
                           v.z * inv * gv.z, v.w * inv * gv.w);
    size_t orow = row;
    if (transpose_in) {
        int s = row >> 2, b = row & 3;               // row = s*B+b
        orow = ((size_t)b << 10) + s;                // out row = b*S+s
    }
    if (out_full)
        *(float4*)&out_full[orow * DMODEL + tid * 4] = o;
    *(float4*)&out_r[orow * DMODEL + tid * 4] =
        make_float4(rnd_tf(o.x), rnd_tf(o.y), rnd_tf(o.z), rnd_tf(o.w));
}

// ---------------- tf32 tensor-core GEMM, 4-stage cp.async + ldmatrix ----------
// C[M,N] = A[M,K] @ W[N,K]^T. A and W pre-rounded tf32 bit patterns.
// 256 threads, 8 warps as 2(m) x 4(n), warp tile 64x32.
// Fragments via ldmatrix.x4 (1 LDSM replaces 4 LDS.32).
// EPI: 0 = +bias ; 1 = +bias,gelu ; 2 = +bias,+res[m*1024+n] ;
//      3 = +bias,+res[m*1024+n], transposed write out[(s*B+b)*D + n]
// RND: round the stored result to tf32.
#define TG_STAGE 2560                 // u32 per array per stage (128*20)
#define TG_BOFF  10240                // sB base offset in u32 (4 stages of A)
template <int EPI, int RND>
__global__ void __launch_bounds__(256, 2)
tgemm_kernel(const float* __restrict__ A, const float* __restrict__ W,
             const float* __restrict__ bias, const float* __restrict__ res,
             float* __restrict__ C, int M, int N, int K) {
    extern __shared__ uint32_t tsm[];
    int tid = threadIdx.x;
    int m0 = blockIdx.y * 128, n0 = blockIdx.x * 128;
    int warp = tid >> 5, lane = tid & 31;
    int wm = (warp & 1) * 64, wn = (warp >> 1) * 32;
    int r = lane >> 2, cq = lane & 3;
    int part = lane >> 3, lr = lane & 7;
    // ldmatrix per-thread address offsets (u32 units, within a stage)
    // A x4 at (i,kk): m0=rows mi..+7 @kk, m1=rows mi+8..+15 @kk, m2/m3 same @kk+4
    int aoff = (wm + (part & 1) * 8 + lr) * 20 + (part >> 1) * 4;
    // B x4 at (jp,kk): m0/m1=rows j(2jp) @kk/kk+4, m2/m3=rows j(2jp+1) @kk/kk+4
    int boff = (wn + (part >> 1) * 8 + lr) * 20 + (part & 1) * 4;

    // cp.async mapping: 512 16B-chunks per matrix per stage; 2 per thread each
    int ar0 = tid >> 2, ak0 = (tid & 3) * 4;
    int ar1 = ar0 + 64;
    const float* Ag0 = A + (size_t)(m0 + ar0) * K + ak0;
    const float* Ag1 = A + (size_t)(m0 + ar1) * K + ak0;
    const float* Wg0 = W + (size_t)(n0 + ar0) * K + ak0;
    const float* Wg1 = W + (size_t)(n0 + ar1) * K + ak0;
    uint32_t sbase = (uint32_t)__cvta_generic_to_shared(tsm);
    uint32_t oa0 = sbase + (ar0 * 20 + ak0) * 4;
    uint32_t oa1 = sbase + (ar1 * 20 + ak0) * 4;
    uint32_t ob0 = sbase + (TG_BOFF + ar0 * 20 + ak0) * 4;
    uint32_t ob1 = sbase + (TG_BOFF + ar1 * 20 + ak0) * 4;

    float acc[4][4][4] = {};
    int T = K >> 4;

    #define TG_PF(g) do {                                   \
        int st_ = (g) & 3; int kof_ = (g) << 4;             \
        uint32_t sof_ = st_ * (TG_STAGE * 4);               \
        cpa16(oa0 + sof_, Ag0 + kof_);                      \
        cpa16(oa1 + sof_, Ag1 + kof_);                      \
        cpa16(ob0 + sof_, Wg0 + kof_);                      \
        cpa16(ob1 + sof_, Wg1 + kof_);                      \
        cpa_commit();                                       \
    } while (0)

    TG_PF(0); TG_PF(1); TG_PF(2);      // K >= 48 always here

    for (int t = 0; t < T; t++) {
        int rem = T - 1 - t;
        if (rem >= 2) cpa_wait<2>();
        else if (rem == 1) cpa_wait<1>();
        else cpa_wait<0>();
        __syncthreads();
        uint32_t aS = sbase + ((t & 3) * TG_STAGE) * 4;
        uint32_t bS = sbase + ((TG_BOFF + (t & 3) * TG_STAGE)) * 4;
        #pragma unroll
        for (int kk = 0; kk < 16; kk += 8) {
            uint32_t af[4][4], bf[4][2];
            #pragma unroll
            for (int i = 0; i < 4; i++)
                ldsm4(af[i][0], af[i][1], af[i][2], af[i][3],
                      aS + (uint32_t)(aoff + i * 320 + kk) * 4);
            #pragma unroll
            for (int jp = 0; jp < 2; jp++)
                ldsm4(bf[2 * jp][0], bf[2 * jp][1],
                      bf[2 * jp + 1][0], bf[2 * jp + 1][1],
                      bS + (uint32_t)(boff + jp * 320 + kk) * 4);   // FIX: 16 rows per jp
            #pragma unroll
            for (int i = 0; i < 4; i++)
                #pragma unroll
                for (int j = 0; j < 4; j++)
                    mma8(acc[i][j], af[i], bf[j]);
        }
        if (t + 3 < T) TG_PF(t + 3);
    }
    // epilogue
    float2 bb[4];
    #pragma unroll
    for (int j = 0; j < 4; j++)
        bb[j] = *(const float2*)&bias[n0 + wn + j * 8 + 2 * cq];
    #pragma unroll
    for (int i = 0; i < 4; i++)
        #pragma unroll
        for (int ph = 0; ph < 2; ph++) {
            int m = m0 + wm + i * 16 + r + ph * 8;
            #pragma unroll
            for (int j = 0; j < 4; j++) {
                int col = n0 + wn + j * 8 + 2 * cq;
                float v0 = acc[i][j][ph * 2 + 0] + bb[j].x;
                float v1 = acc[i][j][ph * 2 + 1] + bb[j].y;
                if (EPI == 1) { v0 = gelu_f(v0); v1 = gelu_f(v1); }
                if (EPI == 2 || EPI == 3) {
                    float2 rr = *(const float2*)&res[(size_t)m * 1024 + col];
                    v0 += rr.x; v1 += rr.y;
                }
                if (RND) { v0 = rnd_tf(v0); v1 = rnd_tf(v1); }
                size_t obp;
                if (EPI == 3) {
                    int b = m >> 10, s = m & 1023;
                    obp = ((size_t)(s * BATCH + b)) * DMODEL + col;
                } else {
                    obp = (size_t)m * N + col;
                }
                *(float2*)&C[obp] = make_float2(v0, v1);
            }
        }
}

// ---------------- qrel: qrel[bh,q,r] = q_head[q,:] . rel_k[r,:] ---------------
__global__ void __launch_bounds__(256)
qrel_kernel(const float* __restrict__ q, const float* __restrict__ relk,
            float* __restrict__ qrel) {
    __shared__ float sR[NREL][65];
    __shared__ float sQ[64][65];
    int bh = blockIdx.y;
    int b = bh >> 4, h = bh & 15;
    int q0 = blockIdx.x * 64;
    int tid = threadIdx.x;
    const float* Q = q + ((size_t)(b * S_LEN) + q0) * DMODEL + h * HDIM;
    for (int i = tid; i < NREL * 64; i += 256) {
        int r = i >> 6, d = i & 63;
        sR[r][d] = relk[i];
    }
    for (int i = tid; i < 64 * 64; i += 256) {
        int r = i >> 6, d = i & 63;
        sQ[r][d] = Q[(size_t)r * DMODEL + d];
    }
    __syncthreads();
    for (int i = tid; i < 64 * NREL; i += 256) {
        int qq = i / NREL, r = i % NREL;
        float s = 0.f;
        #pragma unroll
        for (int d = 0; d < 64; d++) s += sQ[qq][d] * sR[r][d];
        qrel[((size_t)bh * 1024 + q0 + qq) * NREL + r] = s;
    }
}

// ---------------- fused flash attention with relative positions ---------------
// One block = (bh, 128-row q tile). 8 warps, each owns 16 q rows.
// Inputs q/k/v pre-rounded to tf32 bit patterns -> mma consumes raw bits.
#define FO_Q    0
#define FO_P    8704
#define FO_K    17408
#define FO_V    26112
#define FO_QREL 35328
#define FO_RELV 48640
#define FO_END  55508          // * 4 = 222032 bytes

__global__ void __launch_bounds__(256, 1)
flash_kernel(const float* __restrict__ q, const float* __restrict__ k,
             const float* __restrict__ v, const float* __restrict__ qrel,
             const float* __restrict__ relv, float* __restrict__ o) {
    extern __shared__ uint32_t fsm[];
    uint32_t* sQ = fsm + FO_Q;
    uint32_t* sP = fsm + FO_P;
    float* sQrel = (float*)(fsm + FO_QREL);
    float* sRelv = (float*)(fsm + FO_RELV);
    int bh = blockIdx.y;
    int b = bh >> 4, h = bh & 15;
    int q0 = blockIdx.x * 128;
    int tid = threadIdx.x, warp = tid >> 5, lane = tid & 31;
    int r = lane >> 2, cq = lane & 3;
    int wq = warp * 16;                      // warp's local q base

    const float* Qg = q + ((size_t)(b << 10) + q0) * 1024 + h * 64;
    const float* Kg = k + ((size_t)(b << 10)) * 1024 + h * 64;
    const float* Vg = v + ((size_t)(b << 10)) * 1024 + h * 64;
    uint32_t sbase = (uint32_t)__cvta_generic_to_shared(fsm);

    // coop loads: Q tile (already tf32 bits), qrel tile, rel_v table
    for (int i = tid; i < 2048; i += 256) {              // 128 rows x 16 f4
        int row = i >> 4, cg = (i & 15) * 4;
        float4 t = *(const float4*)&Qg[(size_t)row * 1024 + cg];
        sQ[row * 68 + cg + 0] = __float_as_uint(t.x);
        sQ[row * 68 + cg + 1] = __float_as_uint(t.y);
        sQ[row * 68 + cg + 2] = __float_as_uint(t.z);
        sQ[row * 68 + cg + 3] = __float_as_uint(t.w);
    }
    {
        const float* QR = qrel + ((size_t)bh * 1024 + q0) * NREL;
        for (int i = tid; i < 128 * NREL; i += 256)
            sQrel[(i / NREL) * 104 + (i % NREL)] = QR[i];
        for (int i = tid; i < NREL * 64; i += 256)
            sRelv[(i >> 6) * 68 + (i & 63)] = relv[i];
    }

    // K/V tile prefetch: 1024 16B-chunks per array; 4 per thread per array
    #define FL_PF(kt) do {                                                   \
        int buf_ = (kt) & 1;                                                 \
        uint32_t kb_ = sbase + (FO_K + buf_ * 4352) * 4;                     \
        uint32_t vb_ = sbase + (FO_V + buf_ * 4608) * 4;                     \
        const float* Ks_ = Kg + (size_t)((kt) * 64) * 1024;                  \
        const float* Vs_ = Vg + (size_t)((kt) * 64) * 1024;                  \
        _Pragma("unroll")                                                    \
        for (int i_ = 0; i_ < 4; i_++) {                                     \
            int c_ = tid + 256 * i_;                                         \
            int row_ = c_ >> 4, cg_ = (c_ & 15) * 4;                         \
            cpa16(kb_ + (row_ * 68 + cg_) * 4, Ks_ + (size_t)row_ * 1024 + cg_); \
            cpa16(vb_ + (row_ * 72 + cg_) * 4, Vs_ + (size_t)row_ * 1024 + cg_); \
        }                                                                    \
        cpa_commit();                                                        \
    } while (0)

    FL_PF(0);

    float m0_ = -1e30f, m1_ = -1e30f;
    float l0 = 0.f, l1 = 0.f, R0 = 0.f, R1 = 0.f, bs0 = 0.f, bs1 = 0.f;
    float O[8][4] = {};

    for (int kt = 0; kt < 16; kt++) {
        cpa_wait<0>();
        __syncthreads();
        if (kt + 1 < 16) FL_PF(kt + 1);
        const uint32_t* sKc = fsm + FO_K + (kt & 1) * 4352;
        const uint32_t* sVc = fsm + FO_V + (kt & 1) * 4608;
        int k0g = kt * 64;

        // ---- S = Q @ K^T ----
        float sc[8][4] = {};
        #pragma unroll
        for (int kk = 0; kk < 64; kk += 8) {
            uint32_t af[4];
            af[0] = sQ[(wq + r) * 68 + kk + cq];
            af[1] = sQ[(wq + r + 8) * 68 + kk + cq];
            af[2] = sQ[(wq + r) * 68 + kk + cq + 4];
            af[3] = sQ[(wq + r + 8) * 68 + kk + cq + 4];
            #pragma unroll
            for (int j = 0; j < 8; j++) {
                uint32_t bf[2];
                bf[0] = sKc[(8 * j + r) * 68 + kk + cq];
                bf[1] = sKc[(8 * j + r) * 68 + kk + cq + 4];
                mma8(sc[j], af, bf);
            }
        }
        // ---- bias + scale ----
        int row0 = q0 + wq + r, row1 = row0 + 8;
        #pragma unroll
        for (int j = 0; j < 8; j++) {
            #pragma unroll
            for (int e = 0; e < 4; e++) {
                int row_abs = (e < 2) ? row0 : row1;
                int rowl = (e < 2) ? (wq + r) : (wq + r + 8);
                int col_abs = k0g + 8 * j + 2 * cq + (e & 1);
                int d = min(max(col_abs - row_abs, -50), 50) + 50;
                sc[j][e] = (sc[j][e] + sQrel[rowl * 104 + d]) * 0.125f;
            }
        }
        // ---- online softmax stats ----
        float tm0 = -1e30f, tm1 = -1e30f;
        #pragma unroll
        for (int j = 0; j < 8; j++) {
            tm0 = fmaxf(tm0, fmaxf(sc[j][0], sc[j][1]));
            tm1 = fmaxf(tm1, fmaxf(sc[j][2], sc[j][3]));
        }
        tm0 = fmaxf(tm0, __shfl_xor_sync(0xffffffffu, tm0, 1));
        tm0 = fmaxf(tm0, __shfl_xor_sync(0xffffffffu, tm0, 2));
        tm1 = fmaxf(tm1, __shfl_xor_sync(0xffffffffu, tm1, 1));
        tm1 = fmaxf(tm1, __shfl_xor_sync(0xffffffffu, tm1, 2));
        float mn0 = fmaxf(m0_, tm0), mn1 = fmaxf(m1_, tm1);
        float a0 = __expf(m0_ - mn0), a1 = __expf(m1_ - mn1);
        m0_ = mn0; m1_ = mn1;
        float ls0 = 0.f, ls1 = 0.f, rs0 = 0.f, rs1 = 0.f;
        #pragma unroll
        for (int j = 0; j < 8; j++) {
            #pragma unroll
            for (int e = 0; e < 4; e++) {
                int row_abs = (e < 2) ? row0 : row1;
                int col_abs = k0g + 8 * j + 2 * cq + (e & 1);
                float p = __expf(sc[j][e] - ((e < 2) ? mn0 : mn1));
                sc[j][e] = p;
                if (e < 2) { ls0 += p; if (col_abs - row_abs >= 50) rs0 += p; }
                else       { ls1 += p; if (col_abs - row_abs >= 50) rs1 += p; }
            }
        }
        l0 = l0 * a0 + ls0; l1 = l1 * a1 + ls1;
        R0 = R0 * a0 + rs0; R1 = R1 * a1 + rs1;
        bs0 *= a0; bs1 *= a1;
        #pragma unroll
        for (int j = 0; j < 8; j++) {
            O[j][0] *= a0; O[j][1] *= a0; O[j][2] *= a1; O[j][3] *= a1;
        }
        // ---- write p to sP (raw fp32 bits; mma truncates to tf32) ----
        #pragma unroll
        for (int j = 0; j < 8; j++) {
            sP[(wq + r) * 68 + 8 * j + 2 * cq]     = __float_as_uint(sc[j][0]);
            sP[(wq + r) * 68 + 8 * j + 2 * cq + 1] = __float_as_uint(sc[j][1]);
            sP[(wq + r + 8) * 68 + 8 * j + 2 * cq]     = __float_as_uint(sc[j][2]);
            sP[(wq + r + 8) * 68 + 8 * j + 2 * cq + 1] = __float_as_uint(sc[j][3]);
        }
        __syncwarp();
        // ---- near-diagonal band: O += p * rel_v[k-q+50] ----
        if (k0g <= q0 + wq + 15 + 49 && k0g + 63 >= q0 + wq - 49) {
            #pragma unroll
            for (int ph = 0; ph < 2; ph++) {
                int rowl = wq + r + ph * 8;
                int base = (q0 + rowl) - k0g;       // kloc where k == q
                int klo = max(0, base - 49), khi = min(63, base + 49);
                float bsl = 0.f;
                for (int kl = klo; kl <= khi; kl++) {
                    float pv = __uint_as_float(sP[rowl * 68 + kl]);
                    const float* rv = &sRelv[(kl - base + 50) * 68];
                    bsl += pv;
                    #pragma unroll
                    for (int j = 0; j < 8; j++) {
                        int c0 = 8 * j + 2 * cq;
                        O[j][ph * 2 + 0] += pv * rv[c0];
                        O[j][ph * 2 + 1] += pv * rv[c0 + 1];
                    }
                }
                if (ph == 0) bs0 += bsl; else bs1 += bsl;
            }
        }
        // ---- O += P @ V ----
        #pragma unroll
        for (int kk = 0; kk < 64; kk += 8) {
            uint32_t af[4];
            af[0] = sP[(wq + r) * 68 + kk + cq];
            af[1] = sP[(wq + r + 8) * 68 + kk + cq];
            af[2] = sP[(wq + r) * 68 + kk + cq + 4];
            af[3] = sP[(wq + r + 8) * 68 + kk + cq + 4];
            #pragma unroll
            for (int j = 0; j < 8; j++) {
                uint32_t bf[2];
                bf[0] = sVc[(kk + cq) * 72 + 8 * j + r];
                bf[1] = sVc[(kk + cq + 4) * 72 + 8 * j + r];
                mma8(O[j], af, bf);
            }
        }
    }
    // ---- finalize ----
    l0 += __shfl_xor_sync(0xffffffffu, l0, 1);
    l0 += __shfl_xor_sync(0xffffffffu, l0, 2);
    l1 += __shfl_xor_sync(0xffffffffu, l1, 1);
    l1 += __shfl_xor_sync(0xffffffffu, l1, 2);
    R0 += __shfl_xor_sync(0xffffffffu, R0, 1);
    R0 += __shfl_xor_sync(0xffffffffu, R0, 2);
    R1 += __shfl_xor_sync(0xffffffffu, R1, 1);
    R1 += __shfl_xor_sync(0xffffffffu, R1, 2);
    float L0 = l0 - R0 - bs0, L1 = l1 - R1 - bs1;
    float inv0 = 1.0f / l0, inv1 = 1.0f / l1;
    int rowA = q0 + wq + r, rowB = rowA + 8;
    float* oA = o + ((size_t)(b << 10) + rowA) * 1024 + h * 64;
    float* oB = o + ((size_t)(b << 10) + rowB) * 1024 + h * 64;
    #pragma unroll
    for (int j = 0; j < 8; j++) {
        int c0 = 8 * j + 2 * cq;
        float rv0a = sRelv[c0], rv0b = sRelv[c0 + 1];
        float rva = sRelv[100 * 68 + c0], rvb = sRelv[100 * 68 + c0 + 1];
        *(float2*)&oA[c0] = make_float2(
            rnd_tf((O[j][0] + L0 * rv0a + R0 * rva) * inv0),
            rnd_tf((O[j][1] + L0 * rv0b + R0 * rvb) * inv0));
        *(float2*)&oB[c0] = make_float2(
            rnd_tf((O[j][2] + L1 * rv0a + R1 * rva) * inv1),
            rnd_tf((O[j][3] + L1 * rv0b + R1 * rvb) * inv1));
    }
}

// ---------------- host launch -------------------------------------------------
extern "C" void kernel_launch(void* const* d_in, const int* in_sizes, int n_in,
                              void* d_out, int out_size) {
    const float* x     = (const float*)d_in[0];
    const float* Wq    = (const float*)d_in[1];
    const float* bq    = (const float*)d_in[2];
    const float* Wk    = (const float*)d_in[3];
    const float* bk    = (const float*)d_in[4];
    const float* Wv    = (const float*)d_in[5];
    const float* bv    = (const float*)d_in[6];
    const float* Wo    = (const float*)d_in[7];
    const float* bo    = (const float*)d_in[8];
    const float* rel_k = (const float*)d_in[9];
    const float* rel_v = (const float*)d_in[10];
    const float* ga    = (const float*)d_in[11];
    const float* gf    = (const float*)d_in[12];
    const float* W_in  = (const float*)d_in[13];
    const float* b_in  = (const float*)d_in[14];
    const float* W_out = (const float*)d_in[15];
    const float* b_out = (const float*)d_in[16];
    float* out = (float*)d_out;

    float *hn, *hnr, *qb, *kb, *vb, *qr, *ob, *h2, *ffin, *gel, *wr;
    cudaGetSymbolAddress((void**)&hn,   g_hn);
    cudaGetSymbolAddress((void**)&hnr,  g_hnr);
    cudaGetSymbolAddress((void**)&qb,   g_q);
    cudaGetSymbolAddress((void**)&kb,   g_k);
    cudaGetSymbolAddress((void**)&vb,   g_v);
    cudaGetSymbolAddress((void**)&qr,   g_qrel);
    cudaGetSymbolAddress((void**)&ob,   g_o);
    cudaGetSymbolAddress((void**)&h2,   g_h2);
    cudaGetSymbolAddress((void**)&ffin, g_ffin);
    cudaGetSymbolAddress((void**)&gel,  g_gelu);
    cudaGetSymbolAddress((void**)&wr,   g_wr);

    const int TG_SMEM = 20480 * 4;                 // 81920 B
    const int FL_SMEM = FO_END * 4;                // 222032 B
    cudaFuncSetAttribute((const void*)tgemm_kernel<0,1>, cudaFuncAttributeMaxDynamicSharedMemorySize, TG_SMEM);
    cudaFuncSetAttribute((const void*)tgemm_kernel<1,1>, cudaFuncAttributeMaxDynamicSharedMemorySize, TG_SMEM);
    cudaFuncSetAttribute((const void*)tgemm_kernel<2,0>, cudaFuncAttributeMaxDynamicSharedMemorySize, TG_SMEM);
    cudaFuncSetAttribute((const void*)tgemm_kernel<3,0>, cudaFuncAttributeMaxDynamicSharedMemorySize, TG_SMEM);
    cudaFuncSetAttribute((const void*)flash_kernel, cudaFuncAttributeMaxDynamicSharedMemorySize, FL_SMEM);

    // 0. pre-round weights to tf32 (needed: ldmatrix frags can't cvt in-loop)
    const int N1M4 = (1024 * 1024) / 4, N4M4 = (4 * 1024 * 1024) / 4;
    round_tf32_kernel<<<N1M4 / 256, 256>>>((const float4*)Wq,    (float4*)(wr + WOFF_Q),   N1M4);
    round_tf32_kernel<<<N1M4 / 256, 256>>>((const float4*)Wk,    (float4*)(wr + WOFF_K),   N1M4);
    round_tf32_kernel<<<N1M4 / 256, 256>>>((const float4*)Wv,    (float4*)(wr + WOFF_V),   N1M4);
    round_tf32_kernel<<<N1M4 / 256, 256>>>((const float4*)Wo,    (float4*)(wr + WOFF_O),   N1M4);
    round_tf32_kernel<<<N4M4 / 256, 256>>>((const float4*)W_in,  (float4*)(wr + WOFF_IN),  N4M4);
    round_tf32_kernel<<<N4M4 / 256, 256>>>((const float4*)W_out, (float4*)(wr + WOFF_OUT), N4M4);

    // 1. h = rmsnorm(x, g_attn) -> hn (full) + hnr (tf32), [S,B,D]->[B,S,D]
    rmsnorm_kernel<<<M4, 256>>>(x, ga, hn, hnr, 1);
    // 2. q, k, v (stores tf32-rounded)
    dim3 g1(DMODEL / 128, M4 / 128);
    tgemm_kernel<0,1><<<g1, 256, TG_SMEM>>>(hnr, wr + WOFF_Q, bq, nullptr, qb, M4, DMODEL, DMODEL);
    tgemm_kernel<0,1><<<g1, 256, TG_SMEM>>>(hnr, wr + WOFF_K, bk, nullptr, kb, M4, DMODEL, DMODEL);
    tgemm_kernel<0,1><<<g1, 256, TG_SMEM>>>(hnr, wr + WOFF_V, bv, nullptr, vb, M4, DMODEL, DMODEL);
    // 3. qrel
    qrel_kernel<<<dim3(16, 64), 256>>>(qb, rel_k, qr);
    // 4. fused flash attention (stores tf32-rounded o)
    flash_kernel<<<dim3(8, 64), 256, FL_SMEM>>>(qb, kb, vb, qr, rel_v, ob);
    // 5. h2 = hn + o @ Wo^T + bo   (full fp32)
    tgemm_kernel<2,0><<<g1, 256, TG_SMEM>>>(ob, wr + WOFF_O, bo, hn, h2, M4, DMODEL, DMODEL);
    // 6. ffin = rmsnorm(h2, g_ff)  (tf32-rounded only)
    rmsnorm_kernel<<<M4, 256>>>(h2, gf, nullptr, ffin, 0);
    // 7. gelu(ffin @ W_in^T + b_in) (tf32-rounded)
    tgemm_kernel<1,1><<<dim3(DFF / 128, M4 / 128), 256, TG_SMEM>>>(ffin, wr + WOFF_IN, b_in, nullptr,
                                                                   gel, M4, DFF, DMODEL);
    // 8. out = h2 + gel @ W_out^T + b_out  (full fp32, [S,B,D] order)
    tgemm_kernel<3,0><<<g1, 256, TG_SMEM>>>(gel, wr + WOFF_OUT, b_out, h2, out, M4, DMODEL, DFF);
}

// round 13
// speedup vs baseline: 1.0221x; 1.0221x over previous
#include <cuda_runtime.h>
#include <cuda_bf16.h>
#include <math.h>
#include <stdint.h>

// Problem constants
#define S_LEN 1024
#define BATCH 4
#define DMODEL 1024
#define NHEAD 16
#define HDIM 64
#define M4 4096          // BATCH * S_LEN
#define DFF 4096
#define NREL 101         // 2*MAXREL+1

// ---------------- scratch (device globals; no allocations allowed) ----------
__device__ float g_hn  [M4 * DMODEL];          // rmsnorm(x), full fp32 (residual)
__device__ float g_hnr [M4 * DMODEL];          // rmsnorm(x), tf32-rounded (GEMM A)
__device__ float g_q   [M4 * DMODEL];          // tf32-rounded
__device__ float g_k   [M4 * DMODEL];          // tf32-rounded
__device__ float g_v   [M4 * DMODEL];          // tf32-rounded
__device__ float g_qrel[64 * 1024 * NREL];     // [bh, q, r]
__device__ float g_o   [M4 * DMODEL];          // attn head outputs, tf32-rounded
__device__ float g_h2  [M4 * DMODEL];          // h + attn_out, full fp32
__device__ float g_ffin[M4 * DMODEL];          // rmsnorm(h2), tf32-rounded
__device__ float g_gelu[(size_t)M4 * DFF];     // gelu(...), tf32-rounded

// ---------------- helpers ----------------------------------------------------
__device__ __forceinline__ float gelu_f(float x) {
    return 0.5f * x * (1.0f + erff(x * 0.70710678118654752f));
}

__device__ __forceinline__ uint32_t f2tf(float f) {
    uint32_t u;
    asm("cvt.rna.tf32.f32 %0, %1;" : "=r"(u) : "f"(f));
    return u;
}
__device__ __forceinline__ float rnd_tf(float f) {
    return __uint_as_float(f2tf(f));
}

// D = A(16x8, row) * B(8x8, col) + D   (tf32 inputs, f32 accum)
__device__ __forceinline__ void mma8(float* c, const uint32_t* a, const uint32_t* b) {
    asm volatile(
        "mma.sync.aligned.m16n8k8.row.col.f32.tf32.tf32.f32 "
        "{%0,%1,%2,%3}, {%4,%5,%6,%7}, {%8,%9}, {%0,%1,%2,%3};"
        : "+f"(c[0]), "+f"(c[1]), "+f"(c[2]), "+f"(c[3])
        : "r"(a[0]), "r"(a[1]), "r"(a[2]), "r"(a[3]), "r"(b[0]), "r"(b[1]));
}

// ldmatrix x4 over fp32 data: each 8x8 b16 matrix == 8 rows x 4 fp32 cols;
// thread lane r*4+c receives fp32 element [row r][col c] -> tf32 frag layout.
__device__ __forceinline__ void ldsm4(uint32_t& r0, uint32_t& r1,
                                      uint32_t& r2, uint32_t& r3, uint32_t addr) {
    asm volatile("ldmatrix.sync.aligned.m8n8.x4.shared.b16 {%0,%1,%2,%3}, [%4];"
                 : "=r"(r0), "=r"(r1), "=r"(r2), "=r"(r3) : "r"(addr));
}

__device__ __forceinline__ void cpa16(uint32_t smem, const void* gmem) {
    asm volatile("cp.async.cg.shared.global [%0], [%1], 16;\n"
                 :: "r"(smem), "l"(gmem));
}
__device__ __forceinline__ void cpa_commit() {
    asm volatile("cp.async.commit_group;\n");
}
template <int N>
__device__ __forceinline__ void cpa_wait() {
    asm volatile("cp.async.wait_group %0;\n" :: "n"(N));
}

// 256-thread block reduce (8 warps). domax: true -> max, false -> sum.
__device__ __forceinline__ float blk_reduce(float v, float* red, bool domax) {
    #pragma unroll
    for (int o = 16; o > 0; o >>= 1) {
        float u = __shfl_xor_sync(0xffffffffu, v, o);
        v = domax ? fmaxf(v, u) : (v + u);
    }
    __syncthreads();
    if ((threadIdx.x & 31) == 0) red[threadIdx.x >> 5] = v;
    __syncthreads();
    float t = red[0];
    #pragma unroll
    for (int i = 1; i < 8; i++) t = domax ? fmaxf(t, red[i]) : (t + red[i]);
    return t;
}

// ---------------- RMSNorm -----------------------------------------------------
// out_full (may be null): full fp32; out_r: tf32-rounded copy for GEMM input.
__global__ void __launch_bounds__(256)
rmsnorm_kernel(const float* __restrict__ in, const float* __restrict__ g,
               float* __restrict__ out_full, float* __restrict__ out_r,
               int transpose_in) {
    __shared__ float red[8];
    int row = blockIdx.x;
    int tid = threadIdx.x;
    const float* xr = in + (size_t)row * DMODEL;
    float4 v = *(const float4*)&xr[tid * 4];
    float ss = v.x * v.x + v.y * v.y + v.z * v.z + v.w * v.w;
    ss = blk_reduce(ss, red, false);
    float rms = sqrtf(ss) * 0.03125f;                // /sqrt(1024)
    float inv = 1.0f / (rms + 1e-8f);
    float4 gv = *(const float4*)&g[tid * 4];
    float4 o = make_float4(v.x * inv * gv.x, v.y * inv * gv.y,
                           v.z * inv * gv.z, v.w * inv * gv.w);
    size_t orow = row;
    if (transpose_in) {
        int s = row >> 2, b = row & 3;               // row = s*B+b
        orow = ((size_t)b << 10) + s;                // out row = b*S+s
    }
    if (out_full)
        *(float4*)&out_full[orow * DMODEL + tid * 4] = o;
    *(float4*)&out_r[orow * DMODEL + tid * 4] =
        make_float4(rnd_tf(o.x), rnd_tf(o.y), rnd_tf(o.z), rnd_tf(o.w));
}

// ---------------- tf32 tensor-core GEMM, 4-stage cp.async + ldmatrix ----------
// C[M,N] = A[M,K] @ W[N,K]^T.
// A pre-rounded tf32 bits (producers round); W raw fp32 (mma truncates to tf32).
// 256 threads, 8 warps as 2(m) x 4(n), warp tile 64x32.
// Fragments via ldmatrix.x4 (1 LDSM replaces 4 LDS.32).
// EPI: 0 = +bias ; 1 = +bias,gelu ; 2 = +bias,+res[m*1024+n] ;
//      3 = +bias,+res[m*1024+n], transposed write out[(s*B+b)*D + n]
// RND: round the stored result to tf32.
#define TG_STAGE 2560                 // u32 per array per stage (128*20)
#define TG_BOFF  10240                // sB base offset in u32 (4 stages of A)
template <int EPI, int RND>
__global__ void __launch_bounds__(256, 2)
tgemm_kernel(const float* __restrict__ A, const float* __restrict__ W,
             const float* __restrict__ bias, const float* __restrict__ res,
             float* __restrict__ C, int M, int N, int K) {
    extern __shared__ uint32_t tsm[];
    int tid = threadIdx.x;
    int m0 = blockIdx.y * 128, n0 = blockIdx.x * 128;
    int warp = tid >> 5, lane = tid & 31;
    int wm = (warp & 1) * 64, wn = (warp >> 1) * 32;
    int r = lane >> 2, cq = lane & 3;
    int part = lane >> 3, lr = lane & 7;
    // ldmatrix per-thread address offsets (u32 units, within a stage)
    // A x4 at (i,kk): m0=rows mi..+7 @kk, m1=rows mi+8..+15 @kk, m2/m3 same @kk+4
    int aoff = (wm + (part & 1) * 8 + lr) * 20 + (part >> 1) * 4;
    // B x4 at (jp,kk): m0/m1=rows j(2jp) @kk/kk+4, m2/m3=rows j(2jp+1) @kk/kk+4
    int boff = (wn + (part >> 1) * 8 + lr) * 20 + (part & 1) * 4;

    // cp.async mapping: 512 16B-chunks per matrix per stage; 2 per thread each
    int ar0 = tid >> 2, ak0 = (tid & 3) * 4;
    int ar1 = ar0 + 64;
    const float* Ag0 = A + (size_t)(m0 + ar0) * K + ak0;
    const float* Ag1 = A + (size_t)(m0 + ar1) * K + ak0;
    const float* Wg0 = W + (size_t)(n0 + ar0) * K + ak0;
    const float* Wg1 = W + (size_t)(n0 + ar1) * K + ak0;
    uint32_t sbase = (uint32_t)__cvta_generic_to_shared(tsm);
    uint32_t oa0 = sbase + (ar0 * 20 + ak0) * 4;
    uint32_t oa1 = sbase + (ar1 * 20 + ak0) * 4;
    uint32_t ob0 = sbase + (TG_BOFF + ar0 * 20 + ak0) * 4;
    uint32_t ob1 = sbase + (TG_BOFF + ar1 * 20 + ak0) * 4;

    float acc[4][4][4] = {};
    int T = K >> 4;

    #define TG_PF(g) do {                                   \
        int st_ = (g) & 3; int kof_ = (g) << 4;             \
        uint32_t sof_ = st_ * (TG_STAGE * 4);               \
        cpa16(oa0 + sof_, Ag0 + kof_);                      \
        cpa16(oa1 + sof_, Ag1 + kof_);                      \
        cpa16(ob0 + sof_, Wg0 + kof_);                      \
        cpa16(ob1 + sof_, Wg1 + kof_);                      \
        cpa_commit();                                       \
    } while (0)

    TG_PF(0); TG_PF(1); TG_PF(2);      // K >= 48 always here

    for (int t = 0; t < T; t++) {
        int rem = T - 1 - t;
        if (rem >= 2) cpa_wait<2>();
        else if (rem == 1) cpa_wait<1>();
        else cpa_wait<0>();
        __syncthreads();
        uint32_t aS = sbase + ((t & 3) * TG_STAGE) * 4;
        uint32_t bS = sbase + ((TG_BOFF + (t & 3) * TG_STAGE)) * 4;
        #pragma unroll
        for (int kk = 0; kk < 16; kk += 8) {
            uint32_t af[4][4], bf[4][2];
            #pragma unroll
            for (int i = 0; i < 4; i++)
                ldsm4(af[i][0], af[i][1], af[i][2], af[i][3],
                      aS + (uint32_t)(aoff + i * 320 + kk) * 4);
            #pragma unroll
            for (int jp = 0; jp < 2; jp++)
                ldsm4(bf[2 * jp][0], bf[2 * jp][1],
                      bf[2 * jp + 1][0], bf[2 * jp + 1][1],
                      bS + (uint32_t)(boff + jp * 320 + kk) * 4);   // 16 rows per jp
            #pragma unroll
            for (int i = 0; i < 4; i++)
                #pragma unroll
                for (int j = 0; j < 4; j++)
                    mma8(acc[i][j], af[i], bf[j]);
        }
        if (t + 3 < T) TG_PF(t + 3);
    }
    // epilogue
    float2 bb[4];
    #pragma unroll
    for (int j = 0; j < 4; j++)
        bb[j] = *(const float2*)&bias[n0 + wn + j * 8 + 2 * cq];
    #pragma unroll
    for (int i = 0; i < 4; i++)
        #pragma unroll
        for (int ph = 0; ph < 2; ph++) {
            int m = m0 + wm + i * 16 + r + ph * 8;
            #pragma unroll
            for (int j = 0; j < 4; j++) {
                int col = n0 + wn + j * 8 + 2 * cq;
                float v0 = acc[i][j][ph * 2 + 0] + bb[j].x;
                float v1 = acc[i][j][ph * 2 + 1] + bb[j].y;
                if (EPI == 1) { v0 = gelu_f(v0); v1 = gelu_f(v1); }
                if (EPI == 2 || EPI == 3) {
                    float2 rr = *(const float2*)&res[(size_t)m * 1024 + col];
                    v0 += rr.x; v1 += rr.y;
                }
                if (RND) { v0 = rnd_tf(v0); v1 = rnd_tf(v1); }
                size_t obp;
                if (EPI == 3) {
                    int b = m >> 10, s = m & 1023;
                    obp = ((size_t)(s * BATCH + b)) * DMODEL + col;
                } else {
                    obp = (size_t)m * N + col;
                }
                *(float2*)&C[obp] = make_float2(v0, v1);
            }
        }
}

// ---------------- qrel: qrel[bh,q,r] = q_head[q,:] . rel_k[r,:] ---------------
__global__ void __launch_bounds__(256)
qrel_kernel(const float* __restrict__ q, const float* __restrict__ relk,
            float* __restrict__ qrel) {
    __shared__ float sR[NREL][65];
    __shared__ float sQ[64][65];
    int bh = blockIdx.y;
    int b = bh >> 4, h = bh & 15;
    int q0 = blockIdx.x * 64;
    int tid = threadIdx.x;
    const float* Q = q + ((size_t)(b * S_LEN) + q0) * DMODEL + h * HDIM;
    for (int i = tid; i < NREL * 64; i += 256) {
        int r = i >> 6, d = i & 63;
        sR[r][d] = relk[i];
    }
    for (int i = tid; i < 64 * 64; i += 256) {
        int r = i >> 6, d = i & 63;
        sQ[r][d] = Q[(size_t)r * DMODEL + d];
    }
    __syncthreads();
    for (int i = tid; i < 64 * NREL; i += 256) {
        int qq = i / NREL, r = i % NREL;
        float s = 0.f;
        #pragma unroll
        for (int d = 0; d < 64; d++) s += sQ[qq][d] * sR[r][d];
        qrel[((size_t)bh * 1024 + q0 + qq) * NREL + r] = s;
    }
}

// ---------------- fused flash attention with relative positions ---------------
// One block = (bh, 128-row q tile). 8 warps, each owns 16 q rows.
// Inputs q/k/v pre-rounded to tf32 bit patterns -> mma consumes raw bits.
#define FO_Q    0
#define FO_P    8704
#define FO_K    17408
#define FO_V    26112
#define FO_QREL 35328
#define FO_RELV 48640
#define FO_END  55508          // * 4 = 222032 bytes

__global__ void __launch_bounds__(256, 1)
flash_kernel(const float* __restrict__ q, const float* __restrict__ k,
             const float* __restrict__ v, const float* __restrict__ qrel,
             const float* __restrict__ relv, float* __restrict__ o) {
    extern __shared__ uint32_t fsm[];
    uint32_t* sQ = fsm + FO_Q;
    uint32_t* sP = fsm + FO_P;
    float* sQrel = (float*)(fsm + FO_QREL);
    float* sRelv = (float*)(fsm + FO_RELV);
    int bh = blockIdx.y;
    int b = bh >> 4, h = bh & 15;
    int q0 = blockIdx.x * 128;
    int tid = threadIdx.x, warp = tid >> 5, lane = tid & 31;
    int r = lane >> 2, cq = lane & 3;
    int wq = warp * 16;                      // warp's local q base

    const float* Qg = q + ((size_t)(b << 10) + q0) * 1024 + h * 64;
    const float* Kg = k + ((size_t)(b << 10)) * 1024 + h * 64;
    const float* Vg = v + ((size_t)(b << 10)) * 1024 + h * 64;
    uint32_t sbase = (uint32_t)__cvta_generic_to_shared(fsm);

    // coop loads: Q tile (already tf32 bits), qrel tile, rel_v table
    for (int i = tid; i < 2048; i += 256) {              // 128 rows x 16 f4
        int row = i >> 4, cg = (i & 15) * 4;
        float4 t = *(const float4*)&Qg[(size_t)row * 1024 + cg];
        sQ[row * 68 + cg + 0] = __float_as_uint(t.x);
        sQ[row * 68 + cg + 1] = __float_as_uint(t.y);
        sQ[row * 68 + cg + 2] = __float_as_uint(t.z);
        sQ[row * 68 + cg + 3] = __float_as_uint(t.w);
    }
    {
        const float* QR = qrel + ((size_t)bh * 1024 + q0) * NREL;
        for (int i = tid; i < 128 * NREL; i += 256)
            sQrel[(i / NREL) * 104 + (i % NREL)] = QR[i];
        for (int i = tid; i < NREL * 64; i += 256)
            sRelv[(i >> 6) * 68 + (i & 63)] = relv[i];
    }

    // K/V tile prefetch: 1024 16B-chunks per array; 4 per thread per array
    #define FL_PF(kt) do {                                                   \
        int buf_ = (kt) & 1;                                                 \
        uint32_t kb_ = sbase + (FO_K + buf_ * 4352) * 4;                     \
        uint32_t vb_ = sbase + (FO_V + buf_ * 4608) * 4;                     \
        const float* Ks_ = Kg + (size_t)((kt) * 64) * 1024;                  \
        const float* Vs_ = Vg + (size_t)((kt) * 64) * 1024;                  \
        _Pragma("unroll")                                                    \
        for (int i_ = 0; i_ < 4; i_++) {                                     \
            int c_ = tid + 256 * i_;                                         \
            int row_ = c_ >> 4, cg_ = (c_ & 15) * 4;                         \
            cpa16(kb_ + (row_ * 68 + cg_) * 4, Ks_ + (size_t)row_ * 1024 + cg_); \
            cpa16(vb_ + (row_ * 72 + cg_) * 4, Vs_ + (size_t)row_ * 1024 + cg_); \
        }                                                                    \
        cpa_commit();                                                        \
    } while (0)

    FL_PF(0);

    float m0_ = -1e30f, m1_ = -1e30f;
    float l0 = 0.f, l1 = 0.f, R0 = 0.f, R1 = 0.f, bs0 = 0.f, bs1 = 0.f;
    float O[8][4] = {};

    for (int kt = 0; kt < 16; kt++) {
        cpa_wait<0>();
        __syncthreads();
        if (kt + 1 < 16) FL_PF(kt + 1);
        const uint32_t* sKc = fsm + FO_K + (kt & 1) * 4352;
        const uint32_t* sVc = fsm + FO_V + (kt & 1) * 4608;
        int k0g = kt * 64;

        // ---- S = Q @ K^T ----
        float sc[8][4] = {};
        #pragma unroll
        for (int kk = 0; kk < 64; kk += 8) {
            uint32_t af[4];
            af[0] = sQ[(wq + r) * 68 + kk + cq];
            af[1] = sQ[(wq + r + 8) * 68 + kk + cq];
            af[2] = sQ[(wq + r) * 68 + kk + cq + 4];
            af[3] = sQ[(wq + r + 8) * 68 + kk + cq + 4];
            #pragma unroll
            for (int j = 0; j < 8; j++) {
                uint32_t bf[2];
                bf[0] = sKc[(8 * j + r) * 68 + kk + cq];
                bf[1] = sKc[(8 * j + r) * 68 + kk + cq + 4];
                mma8(sc[j], af, bf);
            }
        }
        // ---- bias + scale ----
        int row0 = q0 + wq + r, row1 = row0 + 8;
        #pragma unroll
        for (int j = 0; j < 8; j++) {
            #pragma unroll
            for (int e = 0; e < 4; e++) {
                int row_abs = (e < 2) ? row0 : row1;
                int rowl = (e < 2) ? (wq + r) : (wq + r + 8);
                int col_abs = k0g + 8 * j + 2 * cq + (e & 1);
                int d = min(max(col_abs - row_abs, -50), 50) + 50;
                sc[j][e] = (sc[j][e] + sQrel[rowl * 104 + d]) * 0.125f;
            }
        }
        // ---- online softmax stats ----
        float tm0 = -1e30f, tm1 = -1e30f;
        #pragma unroll
        for (int j = 0; j < 8; j++) {
            tm0 = fmaxf(tm0, fmaxf(sc[j][0], sc[j][1]));
            tm1 = fmaxf(tm1, fmaxf(sc[j][2], sc[j][3]));
        }
        tm0 = fmaxf(tm0, __shfl_xor_sync(0xffffffffu, tm0, 1));
        tm0 = fmaxf(tm0, __shfl_xor_sync(0xffffffffu, tm0, 2));
        tm1 = fmaxf(tm1, __shfl_xor_sync(0xffffffffu, tm1, 1));
        tm1 = fmaxf(tm1, __shfl_xor_sync(0xffffffffu, tm1, 2));
        float mn0 = fmaxf(m0_, tm0), mn1 = fmaxf(m1_, tm1);
        float a0 = __expf(m0_ - mn0), a1 = __expf(m1_ - mn1);
        m0_ = mn0; m1_ = mn1;
        float ls0 = 0.f, ls1 = 0.f, rs0 = 0.f, rs1 = 0.f;
        #pragma unroll
        for (int j = 0; j < 8; j++) {
            #pragma unroll
            for (int e = 0; e < 4; e++) {
                int row_abs = (e < 2) ? row0 : row1;
                int col_abs = k0g + 8 * j + 2 * cq + (e & 1);
                float p = __expf(sc[j][e] - ((e < 2) ? mn0 : mn1));
                sc[j][e] = p;
                if (e < 2) { ls0 += p; if (col_abs - row_abs >= 50) rs0 += p; }
                else       { ls1 += p; if (col_abs - row_abs >= 50) rs1 += p; }
            }
        }
        l0 = l0 * a0 + ls0; l1 = l1 * a1 + ls1;
        R0 = R0 * a0 + rs0; R1 = R1 * a1 + rs1;
        bs0 *= a0; bs1 *= a1;
        #pragma unroll
        for (int j = 0; j < 8; j++) {
            O[j][0] *= a0; O[j][1] *= a0; O[j][2] *= a1; O[j][3] *= a1;
        }
        // ---- write p to sP (raw fp32 bits; mma truncates to tf32) ----
        #pragma unroll
        for (int j = 0; j < 8; j++) {
            sP[(wq + r) * 68 + 8 * j + 2 * cq]     = __float_as_uint(sc[j][0]);
            sP[(wq + r) * 68 + 8 * j + 2 * cq + 1] = __float_as_uint(sc[j][1]);
            sP[(wq + r + 8) * 68 + 8 * j + 2 * cq]     = __float_as_uint(sc[j][2]);
            sP[(wq + r + 8) * 68 + 8 * j + 2 * cq + 1] = __float_as_uint(sc[j][3]);
        }
        __syncwarp();
        // ---- near-diagonal band: O += p * rel_v[k-q+50] ----
        if (k0g <= q0 + wq + 15 + 49 && k0g + 63 >= q0 + wq - 49) {
            #pragma unroll
            for (int ph = 0; ph < 2; ph++) {
                int rowl = wq + r + ph * 8;
                int base = (q0 + rowl) - k0g;       // kloc where k == q
                int klo = max(0, base - 49), khi = min(63, base + 49);
                float bsl = 0.f;
                for (int kl = klo; kl <= khi; kl++) {
                    float pv = __uint_as_float(sP[rowl * 68 + kl]);
                    const float* rv = &sRelv[(kl - base + 50) * 68];
                    bsl += pv;
                    #pragma unroll
                    for (int j = 0; j < 8; j++) {
                        int c0 = 8 * j + 2 * cq;
                        O[j][ph * 2 + 0] += pv * rv[c0];
                        O[j][ph * 2 + 1] += pv * rv[c0 + 1];
                    }
                }
                if (ph == 0) bs0 += bsl; else bs1 += bsl;
            }
        }
        // ---- O += P @ V ----
        #pragma unroll
        for (int kk = 0; kk < 64; kk += 8) {
            uint32_t af[4];
            af[0] = sP[(wq + r) * 68 + kk + cq];
            af[1] = sP[(wq + r + 8) * 68 + kk + cq];
            af[2] = sP[(wq + r) * 68 + kk + cq + 4];
            af[3] = sP[(wq + r + 8) * 68 + kk + cq + 4];
            #pragma unroll
            for (int j = 0; j < 8; j++) {
                uint32_t bf[2];
                bf[0] = sVc[(kk + cq) * 72 + 8 * j + r];
                bf[1] = sVc[(kk + cq + 4) * 72 + 8 * j + r];
                mma8(O[j], af, bf);
            }
        }
    }
    // ---- finalize ----
    l0 += __shfl_xor_sync(0xffffffffu, l0, 1);
    l0 += __shfl_xor_sync(0xffffffffu, l0, 2);
    l1 += __shfl_xor_sync(0xffffffffu, l1, 1);
    l1 += __shfl_xor_sync(0xffffffffu, l1, 2);
    R0 += __shfl_xor_sync(0xffffffffu, R0, 1);
    R0 += __shfl_xor_sync(0xffffffffu, R0, 2);
    R1 += __shfl_xor_sync(0xffffffffu, R1, 1);
    R1 += __shfl_xor_sync(0xffffffffu, R1, 2);
    float L0 = l0 - R0 - bs0, L1 = l1 - R1 - bs1;
    float inv0 = 1.0f / l0, inv1 = 1.0f / l1;
    int rowA = q0 + wq + r, rowB = rowA + 8;
    float* oA = o + ((size_t)(b << 10) + rowA) * 1024 + h * 64;
    float* oB = o + ((size_t)(b << 10) + rowB) * 1024 + h * 64;
    #pragma unroll
    for (int j = 0; j < 8; j++) {
        int c0 = 8 * j + 2 * cq;
        float rv0a = sRelv[c0], rv0b = sRelv[c0 + 1];
        float rva = sRelv[100 * 68 + c0], rvb = sRelv[100 * 68 + c0 + 1];
        *(float2*)&oA[c0] = make_float2(
            rnd_tf((O[j][0] + L0 * rv0a + R0 * rva) * inv0),
            rnd_tf((O[j][1] + L0 * rv0b + R0 * rvb) * inv0));
        *(float2*)&oB[c0] = make_float2(
            rnd_tf((O[j][2] + L1 * rv0a + R1 * rva) * inv1),
            rnd_tf((O[j][3] + L1 * rv0b + R1 * rvb) * inv1));
    }
}

// ---------------- host launch -------------------------------------------------
extern "C" void kernel_launch(void* const* d_in, const int* in_sizes, int n_in,
                              void* d_out, int out_size) {
    const float* x     = (const float*)d_in[0];
    const float* Wq    = (const float*)d_in[1];
    const float* bq    = (const float*)d_in[2];
    const float* Wk    = (const float*)d_in[3];
    const float* bk    = (const float*)d_in[4];
    const float* Wv    = (const float*)d_in[5];
    const float* bv    = (const float*)d_in[6];
    const float* Wo    = (const float*)d_in[7];
    const float* bo    = (const float*)d_in[8];
    const float* rel_k = (const float*)d_in[9];
    const float* rel_v = (const float*)d_in[10];
    const float* ga    = (const float*)d_in[11];
    const float* gf    = (const float*)d_in[12];
    const float* W_in  = (const float*)d_in[13];
    const float* b_in  = (const float*)d_in[14];
    const float* W_out = (const float*)d_in[15];
    const float* b_out = (const float*)d_in[16];
    float* out = (float*)d_out;

    float *hn, *hnr, *qb, *kb, *vb, *qr, *ob, *h2, *ffin, *gel;
    cudaGetSymbolAddress((void**)&hn,   g_hn);
    cudaGetSymbolAddress((void**)&hnr,  g_hnr);
    cudaGetSymbolAddress((void**)&qb,   g_q);
    cudaGetSymbolAddress((void**)&kb,   g_k);
    cudaGetSymbolAddress((void**)&vb,   g_v);
    cudaGetSymbolAddress((void**)&qr,   g_qrel);
    cudaGetSymbolAddress((void**)&ob,   g_o);
    cudaGetSymbolAddress((void**)&h2,   g_h2);
    cudaGetSymbolAddress((void**)&ffin, g_ffin);
    cudaGetSymbolAddress((void**)&gel,  g_gelu);

    const int TG_SMEM = 20480 * 4;                 // 81920 B
    const int FL_SMEM = FO_END * 4;                // 222032 B
    cudaFuncSetAttribute((const void*)tgemm_kernel<0,1>, cudaFuncAttributeMaxDynamicSharedMemorySize, TG_SMEM);
    cudaFuncSetAttribute((const void*)tgemm_kernel<1,1>, cudaFuncAttributeMaxDynamicSharedMemorySize, TG_SMEM);
    cudaFuncSetAttribute((const void*)tgemm_kernel<2,0>, cudaFuncAttributeMaxDynamicSharedMemorySize, TG_SMEM);
    cudaFuncSetAttribute((const void*)tgemm_kernel<3,0>, cudaFuncAttributeMaxDynamicSharedMemorySize, TG_SMEM);
    cudaFuncSetAttribute((const void*)flash_kernel, cudaFuncAttributeMaxDynamicSharedMemorySize, FL_SMEM);

    // 1. h = rmsnorm(x, g_attn) -> hn (full) + hnr (tf32), [S,B,D]->[B,S,D]
    rmsnorm_kernel<<<M4, 256>>>(x, ga, hn, hnr, 1);
    // 2. q, k, v (stores tf32-rounded); W raw (mma truncates)
    dim3 g1(DMODEL / 128, M4 / 128);
    tgemm_kernel<0,1><<<g1, 256, TG_SMEM>>>(hnr, Wq, bq, nullptr, qb, M4, DMODEL, DMODEL);
    tgemm_kernel<0,1><<<g1, 256, TG_SMEM>>>(hnr, Wk, bk, nullptr, kb, M4, DMODEL, DMODEL);
    tgemm_kernel<0,1><<<g1, 256, TG_SMEM>>>(hnr, Wv, bv, nullptr, vb, M4, DMODEL, DMODEL);
    // 3. qrel
    qrel_kernel<<<dim3(16, 64), 256>>>(qb, rel_k, qr);
    // 4. fused flash attention (stores tf32-rounded o)
    flash_kernel<<<dim3(8, 64), 256, FL_SMEM>>>(qb, kb, vb, qr, rel_v, ob);
    // 5. h2 = hn + o @ Wo^T + bo   (full fp32)
    tgemm_kernel<2,0><<<g1, 256, TG_SMEM>>>(ob, Wo, bo, hn, h2, M4, DMODEL, DMODEL);
    // 6. ffin = rmsnorm(h2, g_ff)  (tf32-rounded only)
    rmsnorm_kernel<<<M4, 256>>>(h2, gf, nullptr, ffin, 0);
    // 7. gelu(ffin @ W_in^T + b_in) (tf32-rounded)
    tgemm_kernel<1,1><<<dim3(DFF / 128, M4 / 128), 256, TG_SMEM>>>(ffin, W_in, b_in, nullptr,
                                                                   gel, M4, DFF, DMODEL);
    // 8. out = h2 + gel @ W_out^T + b_out  (full fp32, [S,B,D] order)
    tgemm_kernel<3,0><<<g1, 256, TG_SMEM>>>(gel, W_out, b_out, h2, out, M4, DMODEL, DFF);
}

// round 14
// speedup vs baseline: 1.0687x; 1.0456x over previous
#include <cuda_runtime.h>
#include <cuda_bf16.h>
#include <math.h>
#include <stdint.h>

// Problem constants
#define S_LEN 1024
#define BATCH 4
#define DMODEL 1024
#define NHEAD 16
#define HDIM 64
#define M4 4096          // BATCH * S_LEN
#define DFF 4096
#define NREL 101         // 2*MAXREL+1

// ---------------- scratch (device globals; no allocations allowed) ----------
__device__ float g_hn  [M4 * DMODEL];          // rmsnorm(x), full fp32 (residual)
__device__ float g_hnr [M4 * DMODEL];          // rmsnorm(x), tf32-rounded (GEMM A)
__device__ float g_q   [M4 * DMODEL];          // tf32-rounded
__device__ float g_k   [M4 * DMODEL];          // tf32-rounded
__device__ float g_v   [M4 * DMODEL];          // tf32-rounded
__device__ float g_qrel[64 * 1024 * NREL];     // [bh, q, r]
__device__ float g_o   [M4 * DMODEL];          // attn head outputs, tf32-rounded
__device__ float g_h2  [M4 * DMODEL];          // h + attn_out, full fp32
__device__ float g_ffin[M4 * DMODEL];          // rmsnorm(h2), tf32-rounded
__device__ float g_gelu[(size_t)M4 * DFF];     // gelu(...), tf32-rounded

// ---------------- helpers ----------------------------------------------------
__device__ __forceinline__ float gelu_f(float x) {
    return 0.5f * x * (1.0f + erff(x * 0.70710678118654752f));
}

__device__ __forceinline__ uint32_t f2tf(float f) {
    uint32_t u;
    asm("cvt.rna.tf32.f32 %0, %1;" : "=r"(u) : "f"(f));
    return u;
}
__device__ __forceinline__ float rnd_tf(float f) {
    return __uint_as_float(f2tf(f));
}

// D = A(16x8, row) * B(8x8, col) + D   (tf32 inputs, f32 accum)
__device__ __forceinline__ void mma8(float* c, const uint32_t* a, const uint32_t* b) {
    asm volatile(
        "mma.sync.aligned.m16n8k8.row.col.f32.tf32.tf32.f32 "
        "{%0,%1,%2,%3}, {%4,%5,%6,%7}, {%8,%9}, {%0,%1,%2,%3};"
        : "+f"(c[0]), "+f"(c[1]), "+f"(c[2]), "+f"(c[3])
        : "r"(a[0]), "r"(a[1]), "r"(a[2]), "r"(a[3]), "r"(b[0]), "r"(b[1]));
}

// ldmatrix x4 over fp32 data: each 8x8 b16 matrix == 8 rows x 4 fp32 cols;
// thread lane r*4+c receives fp32 element [row r][col c] -> tf32 frag layout.
__device__ __forceinline__ void ldsm4(uint32_t& r0, uint32_t& r1,
                                      uint32_t& r2, uint32_t& r3, uint32_t addr) {
    asm volatile("ldmatrix.sync.aligned.m8n8.x4.shared.b16 {%0,%1,%2,%3}, [%4];"
                 : "=r"(r0), "=r"(r1), "=r"(r2), "=r"(r3) : "r"(addr));
}

__device__ __forceinline__ void cpa16(uint32_t smem, const void* gmem) {
    asm volatile("cp.async.cg.shared.global [%0], [%1], 16;\n"
                 :: "r"(smem), "l"(gmem));
}
__device__ __forceinline__ void cpa_commit() {
    asm volatile("cp.async.commit_group;\n");
}
template <int N>
__device__ __forceinline__ void cpa_wait() {
    asm volatile("cp.async.wait_group %0;\n" :: "n"(N));
}

// 256-thread block reduce (8 warps). domax: true -> max, false -> sum.
__device__ __forceinline__ float blk_reduce(float v, float* red, bool domax) {
    #pragma unroll
    for (int o = 16; o > 0; o >>= 1) {
        float u = __shfl_xor_sync(0xffffffffu, v, o);
        v = domax ? fmaxf(v, u) : (v + u);
    }
    __syncthreads();
    if ((threadIdx.x & 31) == 0) red[threadIdx.x >> 5] = v;
    __syncthreads();
    float t = red[0];
    #pragma unroll
    for (int i = 1; i < 8; i++) t = domax ? fmaxf(t, red[i]) : (t + red[i]);
    return t;
}

// ---------------- RMSNorm -----------------------------------------------------
// out_full (may be null): full fp32; out_r: tf32-rounded copy for GEMM input.
__global__ void __launch_bounds__(256)
rmsnorm_kernel(const float* __restrict__ in, const float* __restrict__ g,
               float* __restrict__ out_full, float* __restrict__ out_r,
               int transpose_in) {
    __shared__ float red[8];
    int row = blockIdx.x;
    int tid = threadIdx.x;
    const float* xr = in + (size_t)row * DMODEL;
    float4 v = *(const float4*)&xr[tid * 4];
    float ss = v.x * v.x + v.y * v.y + v.z * v.z + v.w * v.w;
    ss = blk_reduce(ss, red, false);
    float rms = sqrtf(ss) * 0.03125f;                // /sqrt(1024)
    float inv = 1.0f / (rms + 1e-8f);
    float4 gv = *(const float4*)&g[tid * 4];
    float4 o = make_float4(v.x * inv * gv.x, v.y * inv * gv.y,
                           v.z * inv * gv.z, v.w * inv * gv.w);
    size_t orow = row;
    if (transpose_in) {
        int s = row >> 2, b = row & 3;               // row = s*B+b
        orow = ((size_t)b << 10) + s;                // out row = b*S+s
    }
    if (out_full)
        *(float4*)&out_full[orow * DMODEL + tid * 4] = o;
    *(float4*)&out_r[orow * DMODEL + tid * 4] =
        make_float4(rnd_tf(o.x), rnd_tf(o.y), rnd_tf(o.z), rnd_tf(o.w));
}

// ---------------- tf32 tensor-core GEMM, KT=32, 3-stage cp.async + ldmatrix ---
// C[M,N] = A[M,K] @ W[N,K]^T.
// A pre-rounded tf32 bits (producers round); W raw fp32 (mma truncates to tf32).
// 256 threads, 8 warps as 2(m) x 4(n), warp tile 64x32.
// Fragments via ldmatrix.x4. One __syncthreads per 32-wide K step.
// EPI: 0 = +bias ; 1 = +bias,gelu ; 2 = +bias,+res[m*1024+n] ;
//      3 = +bias,+res[m*1024+n], transposed write out[(s*B+b)*D + n]
// RND: round the stored result to tf32.
#define TG_RS    36                   // row stride in u32 (32 + pad4)
#define TG_STAGE 4608                 // u32 per array per stage (128*36)
#define TG_BOFF  13824                // sB base offset in u32 (3 stages of A)
#define TG_SMEM  (2 * 13824 * 4)      // 110592 B
template <int EPI, int RND>
__global__ void __launch_bounds__(256, 2)
tgemm_kernel(const float* __restrict__ A, const float* __restrict__ W,
             const float* __restrict__ bias, const float* __restrict__ res,
             float* __restrict__ C, int M, int N, int K) {
    extern __shared__ uint32_t tsm[];
    int tid = threadIdx.x;
    int m0 = blockIdx.y * 128, n0 = blockIdx.x * 128;
    int warp = tid >> 5, lane = tid & 31;
    int wm = (warp & 1) * 64, wn = (warp >> 1) * 32;
    int r = lane >> 2, cq = lane & 3;
    int part = lane >> 3, lr = lane & 7;
    // ldmatrix per-thread address offsets (u32 units, within a stage)
    // A x4 at (i,kk): m0=rows mi..+7 @kk, m1=rows mi+8..+15 @kk, m2/m3 same @kk+4
    int aoff = (wm + (part & 1) * 8 + lr) * TG_RS + (part >> 1) * 4;
    // B x4 at (jp,kk): m0/m1=rows j(2jp) @kk/kk+4, m2/m3=rows j(2jp+1) @kk/kk+4
    int boff = (wn + (part >> 1) * 8 + lr) * TG_RS + (part & 1) * 4;

    // cp.async mapping: 1024 16B-chunks per matrix per stage; 4 per thread each
    int ar0 = tid >> 3, ak0 = (tid & 7) * 4;       // rows ar0 + 32*i, i=0..3
    const float* Ag[4];
    const float* Wg[4];
    uint32_t oa[4], ob[4];
    uint32_t sbase = (uint32_t)__cvta_generic_to_shared(tsm);
    #pragma unroll
    for (int i = 0; i < 4; i++) {
        int rw = ar0 + 32 * i;
        Ag[i] = A + (size_t)(m0 + rw) * K + ak0;
        Wg[i] = W + (size_t)(n0 + rw) * K + ak0;
        oa[i] = sbase + (rw * TG_RS + ak0) * 4;
        ob[i] = sbase + (TG_BOFF + rw * TG_RS + ak0) * 4;
    }

    float acc[4][4][4] = {};
    int T = K >> 5;

    #define TG_PF(g) do {                                   \
        int st_ = (g) % 3; int kof_ = (g) << 5;             \
        uint32_t sof_ = st_ * (TG_STAGE * 4);               \
        _Pragma("unroll")                                   \
        for (int i_ = 0; i_ < 4; i_++) {                    \
            cpa16(oa[i_] + sof_, Ag[i_] + kof_);            \
            cpa16(ob[i_] + sof_, Wg[i_] + kof_);            \
        }                                                   \
        cpa_commit();                                       \
    } while (0)

    TG_PF(0); TG_PF(1);                // K >= 64 always here

    for (int t = 0; t < T; t++) {
        if (t + 1 < T) cpa_wait<1>();
        else cpa_wait<0>();
        __syncthreads();
        uint32_t aS = sbase + ((t % 3) * TG_STAGE) * 4;
        uint32_t bS = sbase + ((TG_BOFF + (t % 3) * TG_STAGE)) * 4;
        #pragma unroll
        for (int kk = 0; kk < 32; kk += 8) {
            uint32_t af[4][4], bf[4][2];
            #pragma unroll
            for (int i = 0; i < 4; i++)
                ldsm4(af[i][0], af[i][1], af[i][2], af[i][3],
                      aS + (uint32_t)(aoff + i * (16 * TG_RS) + kk) * 4);
            #pragma unroll
            for (int jp = 0; jp < 2; jp++)
                ldsm4(bf[2 * jp][0], bf[2 * jp][1],
                      bf[2 * jp + 1][0], bf[2 * jp + 1][1],
                      bS + (uint32_t)(boff + jp * (16 * TG_RS) + kk) * 4);
            #pragma unroll
            for (int i = 0; i < 4; i++)
                #pragma unroll
                for (int j = 0; j < 4; j++)
                    mma8(acc[i][j], af[i], bf[j]);
        }
        if (t + 2 < T) TG_PF(t + 2);
    }
    // epilogue
    float2 bb[4];
    #pragma unroll
    for (int j = 0; j < 4; j++)
        bb[j] = *(const float2*)&bias[n0 + wn + j * 8 + 2 * cq];
    #pragma unroll
    for (int i = 0; i < 4; i++)
        #pragma unroll
        for (int ph = 0; ph < 2; ph++) {
            int m = m0 + wm + i * 16 + r + ph * 8;
            #pragma unroll
            for (int j = 0; j < 4; j++) {
                int col = n0 + wn + j * 8 + 2 * cq;
                float v0 = acc[i][j][ph * 2 + 0] + bb[j].x;
                float v1 = acc[i][j][ph * 2 + 1] + bb[j].y;
                if (EPI == 1) { v0 = gelu_f(v0); v1 = gelu_f(v1); }
                if (EPI == 2 || EPI == 3) {
                    float2 rr = *(const float2*)&res[(size_t)m * 1024 + col];
                    v0 += rr.x; v1 += rr.y;
                }
                if (RND) { v0 = rnd_tf(v0); v1 = rnd_tf(v1); }
                size_t obp;
                if (EPI == 3) {
                    int b = m >> 10, s = m & 1023;
                    obp = ((size_t)(s * BATCH + b)) * DMODEL + col;
                } else {
                    obp = (size_t)m * N + col;
                }
                *(float2*)&C[obp] = make_float2(v0, v1);
            }
        }
}

// ---------------- qrel: qrel[bh,q,r] = q_head[q,:] . rel_k[r,:] ---------------
__global__ void __launch_bounds__(256)
qrel_kernel(const float* __restrict__ q, const float* __restrict__ relk,
            float* __restrict__ qrel) {
    __shared__ float sR[NREL][65];
    __shared__ float sQ[64][65];
    int bh = blockIdx.y;
    int b = bh >> 4, h = bh & 15;
    int q0 = blockIdx.x * 64;
    int tid = threadIdx.x;
    const float* Q = q + ((size_t)(b * S_LEN) + q0) * DMODEL + h * HDIM;
    for (int i = tid; i < NREL * 64; i += 256) {
        int r = i >> 6, d = i & 63;
        sR[r][d] = relk[i];
    }
    for (int i = tid; i < 64 * 64; i += 256) {
        int r = i >> 6, d = i & 63;
        sQ[r][d] = Q[(size_t)r * DMODEL + d];
    }
    __syncthreads();
    for (int i = tid; i < 64 * NREL; i += 256) {
        int qq = i / NREL, r = i % NREL;
        float s = 0.f;
        #pragma unroll
        for (int d = 0; d < 64; d++) s += sQ[qq][d] * sR[r][d];
        qrel[((size_t)bh * 1024 + q0 + qq) * NREL + r] = s;
    }
}

// ---------------- fused flash attention with relative positions ---------------
// One block = (bh, 128-row q tile). 8 warps, each owns 16 q rows.
// Inputs q/k/v pre-rounded to tf32 bit patterns -> mma consumes raw bits.
#define FO_Q    0
#define FO_P    8704
#define FO_K    17408
#define FO_V    26112
#define FO_QREL 35328
#define FO_RELV 48640
#define FO_END  55508          // * 4 = 222032 bytes

__global__ void __launch_bounds__(256, 1)
flash_kernel(const float* __restrict__ q, const float* __restrict__ k,
             const float* __restrict__ v, const float* __restrict__ qrel,
             const float* __restrict__ relv, float* __restrict__ o) {
    extern __shared__ uint32_t fsm[];
    uint32_t* sQ = fsm + FO_Q;
    uint32_t* sP = fsm + FO_P;
    float* sQrel = (float*)(fsm + FO_QREL);
    float* sRelv = (float*)(fsm + FO_RELV);
    int bh = blockIdx.y;
    int b = bh >> 4, h = bh & 15;
    int q0 = blockIdx.x * 128;
    int tid = threadIdx.x, warp = tid >> 5, lane = tid & 31;
    int r = lane >> 2, cq = lane & 3;
    int wq = warp * 16;                      // warp's local q base

    const float* Qg = q + ((size_t)(b << 10) + q0) * 1024 + h * 64;
    const float* Kg = k + ((size_t)(b << 10)) * 1024 + h * 64;
    const float* Vg = v + ((size_t)(b << 10)) * 1024 + h * 64;
    uint32_t sbase = (uint32_t)__cvta_generic_to_shared(fsm);

    // coop loads: Q tile (already tf32 bits), qrel tile, rel_v table
    for (int i = tid; i < 2048; i += 256) {              // 128 rows x 16 f4
        int row = i >> 4, cg = (i & 15) * 4;
        float4 t = *(const float4*)&Qg[(size_t)row * 1024 + cg];
        sQ[row * 68 + cg + 0] = __float_as_uint(t.x);
        sQ[row * 68 + cg + 1] = __float_as_uint(t.y);
        sQ[row * 68 + cg + 2] = __float_as_uint(t.z);
        sQ[row * 68 + cg + 3] = __float_as_uint(t.w);
    }
    {
        const float* QR = qrel + ((size_t)bh * 1024 + q0) * NREL;
        for (int i = tid; i < 128 * NREL; i += 256)
            sQrel[(i / NREL) * 104 + (i % NREL)] = QR[i];
        for (int i = tid; i < NREL * 64; i += 256)
            sRelv[(i >> 6) * 68 + (i & 63)] = relv[i];
    }

    // K/V tile prefetch: 1024 16B-chunks per array; 4 per thread per array
    #define FL_PF(kt) do {                                                   \
        int buf_ = (kt) & 1;                                                 \
        uint32_t kb_ = sbase + (FO_K + buf_ * 4352) * 4;                     \
        uint32_t vb_ = sbase + (FO_V + buf_ * 4608) * 4;                     \
        const float* Ks_ = Kg + (size_t)((kt) * 64) * 1024;                  \
        const float* Vs_ = Vg + (size_t)((kt) * 64) * 1024;                  \
        _Pragma("unroll")                                                    \
        for (int i_ = 0; i_ < 4; i_++) {                                     \
            int c_ = tid + 256 * i_;                                         \
            int row_ = c_ >> 4, cg_ = (c_ & 15) * 4;                         \
            cpa16(kb_ + (row_ * 68 + cg_) * 4, Ks_ + (size_t)row_ * 1024 + cg_); \
            cpa16(vb_ + (row_ * 72 + cg_) * 4, Vs_ + (size_t)row_ * 1024 + cg_); \
        }                                                                    \
        cpa_commit();                                                        \
    } while (0)

    FL_PF(0);

    float m0_ = -1e30f, m1_ = -1e30f;
    float l0 = 0.f, l1 = 0.f, R0 = 0.f, R1 = 0.f, bs0 = 0.f, bs1 = 0.f;
    float O[8][4] = {};

    for (int kt = 0; kt < 16; kt++) {
        cpa_wait<0>();
        __syncthreads();
        if (kt + 1 < 16) FL_PF(kt + 1);
        const uint32_t* sKc = fsm + FO_K + (kt & 1) * 4352;
        const uint32_t* sVc = fsm + FO_V + (kt & 1) * 4608;
        int k0g = kt * 64;

        // ---- S = Q @ K^T ----
        float sc[8][4] = {};
        #pragma unroll
        for (int kk = 0; kk < 64; kk += 8) {
            uint32_t af[4];
            af[0] = sQ[(wq + r) * 68 + kk + cq];
            af[1] = sQ[(wq + r + 8) * 68 + kk + cq];
            af[2] = sQ[(wq + r) * 68 + kk + cq + 4];
            af[3] = sQ[(wq + r + 8) * 68 + kk + cq + 4];
            #pragma unroll
            for (int j = 0; j < 8; j++) {
                uint32_t bf[2];
                bf[0] = sKc[(8 * j + r) * 68 + kk + cq];
                bf[1] = sKc[(8 * j + r) * 68 + kk + cq + 4];
                mma8(sc[j], af, bf);
            }
        }
        // ---- bias + scale ----
        int row0 = q0 + wq + r, row1 = row0 + 8;
        #pragma unroll
        for (int j = 0; j < 8; j++) {
            #pragma unroll
            for (int e = 0; e < 4; e++) {
                int row_abs = (e < 2) ? row0 : row1;
                int rowl = (e < 2) ? (wq + r) : (wq + r + 8);
                int col_abs = k0g + 8 * j + 2 * cq + (e & 1);
                int d = min(max(col_abs - row_abs, -50), 50) + 50;
                sc[j][e] = (sc[j][e] + sQrel[rowl * 104 + d]) * 0.125f;
            }
        }
        // ---- online softmax stats ----
        float tm0 = -1e30f, tm1 = -1e30f;
        #pragma unroll
        for (int j = 0; j < 8; j++) {
            tm0 = fmaxf(tm0, fmaxf(sc[j][0], sc[j][1]));
            tm1 = fmaxf(tm1, fmaxf(sc[j][2], sc[j][3]));
        }
        tm0 = fmaxf(tm0, __shfl_xor_sync(0xffffffffu, tm0, 1));
        tm0 = fmaxf(tm0, __shfl_xor_sync(0xffffffffu, tm0, 2));
        tm1 = fmaxf(tm1, __shfl_xor_sync(0xffffffffu, tm1, 1));
        tm1 = fmaxf(tm1, __shfl_xor_sync(0xffffffffu, tm1, 2));
        float mn0 = fmaxf(m0_, tm0), mn1 = fmaxf(m1_, tm1);
        float a0 = __expf(m0_ - mn0), a1 = __expf(m1_ - mn1);
        m0_ = mn0; m1_ = mn1;
        float ls0 = 0.f, ls1 = 0.f, rs0 = 0.f, rs1 = 0.f;
        #pragma unroll
        for (int j = 0; j < 8; j++) {
            #pragma unroll
            for (int e = 0; e < 4; e++) {
                int row_abs = (e < 2) ? row0 : row1;
                int col_abs = k0g + 8 * j + 2 * cq + (e & 1);
                float p = __expf(sc[j][e] - ((e < 2) ? mn0 : mn1));
                sc[j][e] = p;
                if (e < 2) { ls0 += p; if (col_abs - row_abs >= 50) rs0 += p; }
                else       { ls1 += p; if (col_abs - row_abs >= 50) rs1 += p; }
            }
        }
        l0 = l0 * a0 + ls0; l1 = l1 * a1 + ls1;
        R0 = R0 * a0 + rs0; R1 = R1 * a1 + rs1;
        bs0 *= a0; bs1 *= a1;
        #pragma unroll
        for (int j = 0; j < 8; j++) {
            O[j][0] *= a0; O[j][1] *= a0; O[j][2] *= a1; O[j][3] *= a1;
        }
        // ---- write p to sP (raw fp32 bits; mma truncates to tf32) ----
        #pragma unroll
        for (int j = 0; j < 8; j++) {
            sP[(wq + r) * 68 + 8 * j + 2 * cq]     = __float_as_uint(sc[j][0]);
            sP[(wq + r) * 68 + 8 * j + 2 * cq + 1] = __float_as_uint(sc[j][1]);
            sP[(wq + r + 8) * 68 + 8 * j + 2 * cq]     = __float_as_uint(sc[j][2]);
            sP[(wq + r + 8) * 68 + 8 * j + 2 * cq + 1] = __float_as_uint(sc[j][3]);
        }
        __syncwarp();
        // ---- near-diagonal band: O += p * rel_v[k-q+50] ----
        if (k0g <= q0 + wq + 15 + 49 && k0g + 63 >= q0 + wq - 49) {
            #pragma unroll
            for (int ph = 0; ph < 2; ph++) {
                int rowl = wq + r + ph * 8;
                int base = (q0 + rowl) - k0g;       // kloc where k == q
                int klo = max(0, base - 49), khi = min(63, base + 49);
                float bsl = 0.f;
                for (int kl = klo; kl <= khi; kl++) {
                    float pv = __uint_as_float(sP[rowl * 68 + kl]);
                    const float* rv = &sRelv[(kl - base + 50) * 68];
                    bsl += pv;
                    #pragma unroll
                    for (int j = 0; j < 8; j++) {
                        int c0 = 8 * j + 2 * cq;
                        O[j][ph * 2 + 0] += pv * rv[c0];
                        O[j][ph * 2 + 1] += pv * rv[c0 + 1];
                    }
                }
                if (ph == 0) bs0 += bsl; else bs1 += bsl;
            }
        }
        // ---- O += P @ V ----
        #pragma unroll
        for (int kk = 0; kk < 64; kk += 8) {
            uint32_t af[4];
            af[0] = sP[(wq + r) * 68 + kk + cq];
            af[1] = sP[(wq + r + 8) * 68 + kk + cq];
            af[2] = sP[(wq + r) * 68 + kk + cq + 4];
            af[3] = sP[(wq + r + 8) * 68 + kk + cq + 4];
            #pragma unroll
            for (int j = 0; j < 8; j++) {
                uint32_t bf[2];
                bf[0] = sVc[(kk + cq) * 72 + 8 * j + r];
                bf[1] = sVc[(kk + cq + 4) * 72 + 8 * j + r];
                mma8(O[j], af, bf);
            }
        }
    }
    // ---- finalize ----
    l0 += __shfl_xor_sync(0xffffffffu, l0, 1);
    l0 += __shfl_xor_sync(0xffffffffu, l0, 2);
    l1 += __shfl_xor_sync(0xffffffffu, l1, 1);
    l1 += __shfl_xor_sync(0xffffffffu, l1, 2);
    R0 += __shfl_xor_sync(0xffffffffu, R0, 1);
    R0 += __shfl_xor_sync(0xffffffffu, R0, 2);
    R1 += __shfl_xor_sync(0xffffffffu, R1, 1);
    R1 += __shfl_xor_sync(0xffffffffu, R1, 2);
    float L0 = l0 - R0 - bs0, L1 = l1 - R1 - bs1;
    float inv0 = 1.0f / l0, inv1 = 1.0f / l1;
    int rowA = q0 + wq + r, rowB = rowA + 8;
    float* oA = o + ((size_t)(b << 10) + rowA) * 1024 + h * 64;
    float* oB = o + ((size_t)(b << 10) + rowB) * 1024 + h * 64;
    #pragma unroll
    for (int j = 0; j < 8; j++) {
        int c0 = 8 * j + 2 * cq;
        float rv0a = sRelv[c0], rv0b = sRelv[c0 + 1];
        float rva = sRelv[100 * 68 + c0], rvb = sRelv[100 * 68 + c0 + 1];
        *(float2*)&oA[c0] = make_float2(
            rnd_tf((O[j][0] + L0 * rv0a + R0 * rva) * inv0),
            rnd_tf((O[j][1] + L0 * rv0b + R0 * rvb) * inv0));
        *(float2*)&oB[c0] = make_float2(
            rnd_tf((O[j][2] + L1 * rv0a + R1 * rva) * inv1),
            rnd_tf((O[j][3] + L1 * rv0b + R1 * rvb) * inv1));
    }
}

// ---------------- host launch -------------------------------------------------
extern "C" void kernel_launch(void* const* d_in, const int* in_sizes, int n_in,
                              void* d_out, int out_size) {
    const float* x     = (const float*)d_in[0];
    const float* Wq    = (const float*)d_in[1];
    const float* bq    = (const float*)d_in[2];
    const float* Wk    = (const float*)d_in[3];
    const float* bk    = (const float*)d_in[4];
    const float* Wv    = (const float*)d_in[5];
    const float* bv    = (const float*)d_in[6];
    const float* Wo    = (const float*)d_in[7];
    const float* bo    = (const float*)d_in[8];
    const float* rel_k = (const float*)d_in[9];
    const float* rel_v = (const float*)d_in[10];
    const float* ga    = (const float*)d_in[11];
    const float* gf    = (const float*)d_in[12];
    const float* W_in  = (const float*)d_in[13];
    const float* b_in  = (const float*)d_in[14];
    const float* W_out = (const float*)d_in[15];
    const float* b_out = (const float*)d_in[16];
    float* out = (float*)d_out;

    float *hn, *hnr, *qb, *kb, *vb, *qr, *ob, *h2, *ffin, *gel;
    cudaGetSymbolAddress((void**)&hn,   g_hn);
    cudaGetSymbolAddress((void**)&hnr,  g_hnr);
    cudaGetSymbolAddress((void**)&qb,   g_q);
    cudaGetSymbolAddress((void**)&kb,   g_k);
    cudaGetSymbolAddress((void**)&vb,   g_v);
    cudaGetSymbolAddress((void**)&qr,   g_qrel);
    cudaGetSymbolAddress((void**)&ob,   g_o);
    cudaGetSymbolAddress((void**)&h2,   g_h2);
    cudaGetSymbolAddress((void**)&ffin, g_ffin);
    cudaGetSymbolAddress((void**)&gel,  g_gelu);

    const int FL_SMEM = FO_END * 4;                // 222032 B
    cudaFuncSetAttribute((const void*)tgemm_kernel<0,1>, cudaFuncAttributeMaxDynamicSharedMemorySize, TG_SMEM);
    cudaFuncSetAttribute((const void*)tgemm_kernel<1,1>, cudaFuncAttributeMaxDynamicSharedMemorySize, TG_SMEM);
    cudaFuncSetAttribute((const void*)tgemm_kernel<2,0>, cudaFuncAttributeMaxDynamicSharedMemorySize, TG_SMEM);
    cudaFuncSetAttribute((const void*)tgemm_kernel<3,0>, cudaFuncAttributeMaxDynamicSharedMemorySize, TG_SMEM);
    cudaFuncSetAttribute((const void*)flash_kernel, cudaFuncAttributeMaxDynamicSharedMemorySize, FL_SMEM);

    // 1. h = rmsnorm(x, g_attn) -> hn (full) + hnr (tf32), [S,B,D]->[B,S,D]
    rmsnorm_kernel<<<M4, 256>>>(x, ga, hn, hnr, 1);
    // 2. q, k, v (stores tf32-rounded); W raw (mma truncates)
    dim3 g1(DMODEL / 128, M4 / 128);
    tgemm_kernel<0,1><<<g1, 256, TG_SMEM>>>(hnr, Wq, bq, nullptr, qb, M4, DMODEL, DMODEL);
    tgemm_kernel<0,1><<<g1, 256, TG_SMEM>>>(hnr, Wk, bk, nullptr, kb, M4, DMODEL, DMODEL);
    tgemm_kernel<0,1><<<g1, 256, TG_SMEM>>>(hnr, Wv, bv, nullptr, vb, M4, DMODEL, DMODEL);
    // 3. qrel
    qrel_kernel<<<dim3(16, 64), 256>>>(qb, rel_k, qr);
    // 4. fused flash attention (stores tf32-rounded o)
    flash_kernel<<<dim3(8, 64), 256, FL_SMEM>>>(qb, kb, vb, qr, rel_v, ob);
    // 5. h2 = hn + o @ Wo^T + bo   (full fp32)
    tgemm_kernel<2,0><<<g1, 256, TG_SMEM>>>(ob, Wo, bo, hn, h2, M4, DMODEL, DMODEL);
    // 6. ffin = rmsnorm(h2, g_ff)  (tf32-rounded only)
    rmsnorm_kernel<<<M4, 256>>>(h2, gf, nullptr, ffin, 0);
    // 7. gelu(ffin @ W_in^T + b_in) (tf32-rounded)
    tgemm_kernel<1,1><<<dim3(DFF / 128, M4 / 128), 256, TG_SMEM>>>(ffin, W_in, b_in, nullptr,
                                                                   gel, M4, DFF, DMODEL);
    // 8. out = h2 + gel @ W_out^T + b_out  (full fp32, [S,B,D] order)
    tgemm_kernel<3,0><<<g1, 256, TG_SMEM>>>(gel, W_out, b_out, h2, out, M4, DMODEL, DFF);
}

// round 15
// speedup vs baseline: 1.1639x; 1.0892x over previous
#include <cuda_runtime.h>
#include <cuda_bf16.h>
#include <math.h>
#include <stdint.h>

// Problem constants
#define S_LEN 1024
#define BATCH 4
#define DMODEL 1024
#define NHEAD 16
#define HDIM 64
#define M4 4096          // BATCH * S_LEN
#define DFF 4096
#define NREL 101         // 2*MAXREL+1

// ---------------- scratch (device globals; no allocations allowed) ----------
__device__ float g_hn  [M4 * DMODEL];          // rmsnorm(x), full fp32 (residual)
__device__ __nv_bfloat16 g_hnbf[M4 * DMODEL];  // rmsnorm(x), bf16 (QKV GEMM A)
__device__ float g_q   [M4 * DMODEL];          // tf32-rounded
__device__ float g_k   [M4 * DMODEL];          // tf32-rounded
__device__ float g_v   [M4 * DMODEL];          // tf32-rounded
__device__ float g_qrel[64 * 1024 * NREL];     // [bh, q, r]
__device__ __nv_bfloat16 g_obf[M4 * DMODEL];   // attn head outputs, bf16 (Wo A)
__device__ float g_h2  [M4 * DMODEL];          // h + attn_out, full fp32
__device__ float g_ffin[M4 * DMODEL];          // rmsnorm(h2), tf32-rounded
__device__ float g_gelu[(size_t)M4 * DFF];     // gelu(...), tf32-rounded
__device__ __nv_bfloat16 g_wbf[4 * 1024 * 1024]; // bf16 attention weights
#define WOFF_Q   0
#define WOFF_K   (1024*1024)
#define WOFF_V   (2*1024*1024)
#define WOFF_O   (3*1024*1024)

// ---------------- helpers ----------------------------------------------------
__device__ __forceinline__ float gelu_f(float x) {
    return 0.5f * x * (1.0f + erff(x * 0.70710678118654752f));
}

__device__ __forceinline__ uint32_t f2tf(float f) {
    uint32_t u;
    asm("cvt.rna.tf32.f32 %0, %1;" : "=r"(u) : "f"(f));
    return u;
}
__device__ __forceinline__ float rnd_tf(float f) {
    return __uint_as_float(f2tf(f));
}

// D = A(16x8, row) * B(8x8, col) + D   (tf32 inputs, f32 accum)
__device__ __forceinline__ void mma8(float* c, const uint32_t* a, const uint32_t* b) {
    asm volatile(
        "mma.sync.aligned.m16n8k8.row.col.f32.tf32.tf32.f32 "
        "{%0,%1,%2,%3}, {%4,%5,%6,%7}, {%8,%9}, {%0,%1,%2,%3};"
        : "+f"(c[0]), "+f"(c[1]), "+f"(c[2]), "+f"(c[3])
        : "r"(a[0]), "r"(a[1]), "r"(a[2]), "r"(a[3]), "r"(b[0]), "r"(b[1]));
}

// D = A(16x16, row) * B(16x8, col) + D   (bf16 inputs, f32 accum)
__device__ __forceinline__ void mma16b(float* c, const uint32_t* a, const uint32_t* b) {
    asm volatile(
        "mma.sync.aligned.m16n8k16.row.col.f32.bf16.bf16.f32 "
        "{%0,%1,%2,%3}, {%4,%5,%6,%7}, {%8,%9}, {%0,%1,%2,%3};"
        : "+f"(c[0]), "+f"(c[1]), "+f"(c[2]), "+f"(c[3])
        : "r"(a[0]), "r"(a[1]), "r"(a[2]), "r"(a[3]), "r"(b[0]), "r"(b[1]));
}

// ldmatrix x4 (b16 mode; also used over fp32 data for tf32 frags)
__device__ __forceinline__ void ldsm4(uint32_t& r0, uint32_t& r1,
                                      uint32_t& r2, uint32_t& r3, uint32_t addr) {
    asm volatile("ldmatrix.sync.aligned.m8n8.x4.shared.b16 {%0,%1,%2,%3}, [%4];"
                 : "=r"(r0), "=r"(r1), "=r"(r2), "=r"(r3) : "r"(addr));
}

__device__ __forceinline__ void cpa16(uint32_t smem, const void* gmem) {
    asm volatile("cp.async.cg.shared.global [%0], [%1], 16;\n"
                 :: "r"(smem), "l"(gmem));
}
__device__ __forceinline__ void cpa_commit() {
    asm volatile("cp.async.commit_group;\n");
}
template <int N>
__device__ __forceinline__ void cpa_wait() {
    asm volatile("cp.async.wait_group %0;\n" :: "n"(N));
}

// 256-thread block reduce (8 warps). domax: true -> max, false -> sum.
__device__ __forceinline__ float blk_reduce(float v, float* red, bool domax) {
    #pragma unroll
    for (int o = 16; o > 0; o >>= 1) {
        float u = __shfl_xor_sync(0xffffffffu, v, o);
        v = domax ? fmaxf(v, u) : (v + u);
    }
    __syncthreads();
    if ((threadIdx.x & 31) == 0) red[threadIdx.x >> 5] = v;
    __syncthreads();
    float t = red[0];
    #pragma unroll
    for (int i = 1; i < 8; i++) t = domax ? fmaxf(t, red[i]) : (t + red[i]);
    return t;
}

// ---------------- bf16 pre-rounding (attention weights) -----------------------
__global__ void __launch_bounds__(256)
round_bf16_kernel(const float4* __restrict__ in, __nv_bfloat16* __restrict__ out,
                  int n4) {
    int i = blockIdx.x * 256 + threadIdx.x;
    if (i < n4) {
        float4 v = in[i];
        __nv_bfloat162 lo = __floats2bfloat162_rn(v.x, v.y);
        __nv_bfloat162 hi = __floats2bfloat162_rn(v.z, v.w);
        *(__nv_bfloat162*)&out[(size_t)i * 4]     = lo;
        *(__nv_bfloat162*)&out[(size_t)i * 4 + 2] = hi;
    }
}

// ---------------- RMSNorm -----------------------------------------------------
// out_full: fp32 (residual); out_r: tf32-rounded fp32; out_bf: bf16. Any may be null.
__global__ void __launch_bounds__(256)
rmsnorm_kernel(const float* __restrict__ in, const float* __restrict__ g,
               float* __restrict__ out_full, float* __restrict__ out_r,
               __nv_bfloat16* __restrict__ out_bf, int transpose_in) {
    __shared__ float red[8];
    int row = blockIdx.x;
    int tid = threadIdx.x;
    const float* xr = in + (size_t)row * DMODEL;
    float4 v = *(const float4*)&xr[tid * 4];
    float ss = v.x * v.x + v.y * v.y + v.z * v.z + v.w * v.w;
    ss = blk_reduce(ss, red, false);
    float rms = sqrtf(ss) * 0.03125f;                // /sqrt(1024)
    float inv = 1.0f / (rms + 1e-8f);
    float4 gv = *(const float4*)&g[tid * 4];
    float4 o = make_float4(v.x * inv * gv.x, v.y * inv * gv.y,
                           v.z * inv * gv.z, v.w * inv * gv.w);
    size_t orow = row;
    if (transpose_in) {
        int s = row >> 2, b = row & 3;               // row = s*B+b
        orow = ((size_t)b << 10) + s;                // out row = b*S+s
    }
    if (out_full)
        *(float4*)&out_full[orow * DMODEL + tid * 4] = o;
    if (out_r)
        *(float4*)&out_r[orow * DMODEL + tid * 4] =
            make_float4(rnd_tf(o.x), rnd_tf(o.y), rnd_tf(o.z), rnd_tf(o.w));
    if (out_bf) {
        *(__nv_bfloat162*)&out_bf[orow * DMODEL + tid * 4] =
            __floats2bfloat162_rn(o.x, o.y);
        *(__nv_bfloat162*)&out_bf[orow * DMODEL + tid * 4 + 2] =
            __floats2bfloat162_rn(o.z, o.w);
    }
}

// ---------------- tf32 tensor-core GEMM, KT=32, 3-stage cp.async + ldmatrix ---
// (unchanged from R14 winner; used for FFN path)
#define TG_RS    36                   // row stride in u32 (32 + pad4)
#define TG_STAGE 4608                 // u32 per array per stage (128*36)
#define TG_BOFF  13824                // sB base offset in u32 (3 stages of A)
#define TG_SMEM  (2 * 13824 * 4)      // 110592 B
template <int EPI, int RND>
__global__ void __launch_bounds__(256, 2)
tgemm_kernel(const float* __restrict__ A, const float* __restrict__ W,
             const float* __restrict__ bias, const float* __restrict__ res,
             float* __restrict__ C, int M, int N, int K) {
    extern __shared__ uint32_t tsm[];
    int tid = threadIdx.x;
    int m0 = blockIdx.y * 128, n0 = blockIdx.x * 128;
    int warp = tid >> 5, lane = tid & 31;
    int wm = (warp & 1) * 64, wn = (warp >> 1) * 32;
    int r = lane >> 2, cq = lane & 3;
    int part = lane >> 3, lr = lane & 7;
    int aoff = (wm + (part & 1) * 8 + lr) * TG_RS + (part >> 1) * 4;
    int boff = (wn + (part >> 1) * 8 + lr) * TG_RS + (part & 1) * 4;

    int ar0 = tid >> 3, ak0 = (tid & 7) * 4;       // rows ar0 + 32*i, i=0..3
    const float* Ag[4];
    const float* Wg[4];
    uint32_t oa[4], ob[4];
    uint32_t sbase = (uint32_t)__cvta_generic_to_shared(tsm);
    #pragma unroll
    for (int i = 0; i < 4; i++) {
        int rw = ar0 + 32 * i;
        Ag[i] = A + (size_t)(m0 + rw) * K + ak0;
        Wg[i] = W + (size_t)(n0 + rw) * K + ak0;
        oa[i] = sbase + (rw * TG_RS + ak0) * 4;
        ob[i] = sbase + (TG_BOFF + rw * TG_RS + ak0) * 4;
    }

    float acc[4][4][4] = {};
    int T = K >> 5;

    #define TG_PF(g) do {                                   \
        int st_ = (g) % 3; int kof_ = (g) << 5;             \
        uint32_t sof_ = st_ * (TG_STAGE * 4);               \
        _Pragma("unroll")                                   \
        for (int i_ = 0; i_ < 4; i_++) {                    \
            cpa16(oa[i_] + sof_, Ag[i_] + kof_);            \
            cpa16(ob[i_] + sof_, Wg[i_] + kof_);            \
        }                                                   \
        cpa_commit();                                       \
    } while (0)

    TG_PF(0); TG_PF(1);

    for (int t = 0; t < T; t++) {
        if (t + 1 < T) cpa_wait<1>();
        else cpa_wait<0>();
        __syncthreads();
        uint32_t aS = sbase + ((t % 3) * TG_STAGE) * 4;
        uint32_t bS = sbase + ((TG_BOFF + (t % 3) * TG_STAGE)) * 4;
        #pragma unroll
        for (int kk = 0; kk < 32; kk += 8) {
            uint32_t af[4][4], bf[4][2];
            #pragma unroll
            for (int i = 0; i < 4; i++)
                ldsm4(af[i][0], af[i][1], af[i][2], af[i][3],
                      aS + (uint32_t)(aoff + i * (16 * TG_RS) + kk) * 4);
            #pragma unroll
            for (int jp = 0; jp < 2; jp++)
                ldsm4(bf[2 * jp][0], bf[2 * jp][1],
                      bf[2 * jp + 1][0], bf[2 * jp + 1][1],
                      bS + (uint32_t)(boff + jp * (16 * TG_RS) + kk) * 4);
            #pragma unroll
            for (int i = 0; i < 4; i++)
                #pragma unroll
                for (int j = 0; j < 4; j++)
                    mma8(acc[i][j], af[i], bf[j]);
        }
        if (t + 2 < T) TG_PF(t + 2);
    }
    float2 bb[4];
    #pragma unroll
    for (int j = 0; j < 4; j++)
        bb[j] = *(const float2*)&bias[n0 + wn + j * 8 + 2 * cq];
    #pragma unroll
    for (int i = 0; i < 4; i++)
        #pragma unroll
        for (int ph = 0; ph < 2; ph++) {
            int m = m0 + wm + i * 16 + r + ph * 8;
            #pragma unroll
            for (int j = 0; j < 4; j++) {
                int col = n0 + wn + j * 8 + 2 * cq;
                float v0 = acc[i][j][ph * 2 + 0] + bb[j].x;
                float v1 = acc[i][j][ph * 2 + 1] + bb[j].y;
                if (EPI == 1) { v0 = gelu_f(v0); v1 = gelu_f(v1); }
                if (EPI == 2 || EPI == 3) {
                    float2 rr = *(const float2*)&res[(size_t)m * 1024 + col];
                    v0 += rr.x; v1 += rr.y;
                }
                if (RND) { v0 = rnd_tf(v0); v1 = rnd_tf(v1); }
                size_t obp;
                if (EPI == 3) {
                    int b = m >> 10, s = m & 1023;
                    obp = ((size_t)(s * BATCH + b)) * DMODEL + col;
                } else {
                    obp = (size_t)m * N + col;
                }
                *(float2*)&C[obp] = make_float2(v0, v1);
            }
        }
}

// ---------------- bf16 tensor-core GEMM, KT=64, 3-stage cp.async + ldmatrix ---
// C[M,N] = A[M,K] @ W[N,K]^T, A/W bf16, fp32 accum. Same smem bytes as tgemm.
// EPI: 0 = +bias, store rnd_tf fp32 ; 2 = +bias,+res, store full fp32
#define BG_RS    72                   // row stride in halves (64 + pad8) = 144B
template <int EPI>
__global__ void __launch_bounds__(256, 2)
bgemm_kernel(const __nv_bfloat16* __restrict__ A,
             const __nv_bfloat16* __restrict__ W,
             const float* __restrict__ bias, const float* __restrict__ res,
             float* __restrict__ C, int M, int N, int K) {
    extern __shared__ uint32_t tsm[];
    int tid = threadIdx.x;
    int m0 = blockIdx.y * 128, n0 = blockIdx.x * 128;
    int warp = tid >> 5, lane = tid & 31;
    int wm = (warp & 1) * 64, wn = (warp >> 1) * 32;
    int r = lane >> 2, cq = lane & 3;
    int part = lane >> 3, lr = lane & 7;
    // ldmatrix byte offsets within a stage (b16 data, 144 B/row)
    int aoffB = (wm + (part & 1) * 8 + lr) * 144 + (part >> 1) * 16;
    int boffB = (wn + (part >> 1) * 8 + lr) * 144 + (part & 1) * 16;

    // cp.async: 128 rows x 128 B per matrix per stage = 1024 chunks; 4/thread
    int ar0 = tid >> 3, akh = (tid & 7) * 8;       // halves
    const __nv_bfloat16* Ag[4];
    const __nv_bfloat16* Wg[4];
    uint32_t oa[4], ob[4];
    uint32_t sbase = (uint32_t)__cvta_generic_to_shared(tsm);
    #pragma unroll
    for (int i = 0; i < 4; i++) {
        int rw = ar0 + 32 * i;
        Ag[i] = A + (size_t)(m0 + rw) * K + akh;
        Wg[i] = W + (size_t)(n0 + rw) * K + akh;
        oa[i] = sbase + rw * 144 + akh * 2;
        ob[i] = sbase + TG_BOFF * 4 + rw * 144 + akh * 2;
    }

    float acc[4][4][4] = {};
    int T = K >> 6;                    // KT = 64 halves

    #define BG_PF(g) do {                                   \
        int st_ = (g) % 3; int kof_ = (g) << 6;             \
        uint32_t sof_ = st_ * (TG_STAGE * 4);               \
        _Pragma("unroll")                                   \
        for (int i_ = 0; i_ < 4; i_++) {                    \
            cpa16(oa[i_] + sof_, Ag[i_] + kof_);            \
            cpa16(ob[i_] + sof_, Wg[i_] + kof_);            \
        }                                                   \
        cpa_commit();                                       \
    } while (0)

    BG_PF(0); BG_PF(1);                // K >= 128 always

    for (int t = 0; t < T; t++) {
        if (t + 1 < T) cpa_wait<1>();
        else cpa_wait<0>();
        __syncthreads();
        uint32_t aS = sbase + ((t % 3) * TG_STAGE) * 4;
        uint32_t bS = sbase + ((TG_BOFF + (t % 3) * TG_STAGE)) * 4;
        #pragma unroll
        for (int kk = 0; kk < 64; kk += 16) {     // 4 k16 steps
            uint32_t af[4][4], bf[4][2];
            #pragma unroll
            for (int i = 0; i < 4; i++)
                ldsm4(af[i][0], af[i][1], af[i][2], af[i][3],
                      aS + (uint32_t)(aoffB + i * (16 * 144) + kk * 2));
            #pragma unroll
            for (int jp = 0; jp < 2; jp++)
                ldsm4(bf[2 * jp][0], bf[2 * jp][1],
                      bf[2 * jp + 1][0], bf[2 * jp + 1][1],
                      bS + (uint32_t)(boffB + jp * (16 * 144) + kk * 2));
            #pragma unroll
            for (int i = 0; i < 4; i++)
                #pragma unroll
                for (int j = 0; j < 4; j++)
                    mma16b(acc[i][j], af[i], bf[j]);
        }
        if (t + 2 < T) BG_PF(t + 2);
    }
    // epilogue (same output mapping as tgemm)
    float2 bb[4];
    #pragma unroll
    for (int j = 0; j < 4; j++)
        bb[j] = *(const float2*)&bias[n0 + wn + j * 8 + 2 * cq];
    #pragma unroll
    for (int i = 0; i < 4; i++)
        #pragma unroll
        for (int ph = 0; ph < 2; ph++) {
            int m = m0 + wm + i * 16 + r + ph * 8;
            #pragma unroll
            for (int j = 0; j < 4; j++) {
                int col = n0 + wn + j * 8 + 2 * cq;
                float v0 = acc[i][j][ph * 2 + 0] + bb[j].x;
                float v1 = acc[i][j][ph * 2 + 1] + bb[j].y;
                if (EPI == 2) {
                    float2 rr = *(const float2*)&res[(size_t)m * 1024 + col];
                    v0 += rr.x; v1 += rr.y;
                } else {
                    v0 = rnd_tf(v0); v1 = rnd_tf(v1);
                }
                *(float2*)&C[(size_t)m * N + col] = make_float2(v0, v1);
            }
        }
}

// ---------------- qrel: qrel[bh,q,r] = q_head[q,:] . rel_k[r,:] ---------------
__global__ void __launch_bounds__(256)
qrel_kernel(const float* __restrict__ q, const float* __restrict__ relk,
            float* __restrict__ qrel) {
    __shared__ float sR[NREL][65];
    __shared__ float sQ[64][65];
    int bh = blockIdx.y;
    int b = bh >> 4, h = bh & 15;
    int q0 = blockIdx.x * 64;
    int tid = threadIdx.x;
    const float* Q = q + ((size_t)(b * S_LEN) + q0) * DMODEL + h * HDIM;
    for (int i = tid; i < NREL * 64; i += 256) {
        int r = i >> 6, d = i & 63;
        sR[r][d] = relk[i];
    }
    for (int i = tid; i < 64 * 64; i += 256) {
        int r = i >> 6, d = i & 63;
        sQ[r][d] = Q[(size_t)r * DMODEL + d];
    }
    __syncthreads();
    for (int i = tid; i < 64 * NREL; i += 256) {
        int qq = i / NREL, r = i % NREL;
        float s = 0.f;
        #pragma unroll
        for (int d = 0; d < 64; d++) s += sQ[qq][d] * sR[r][d];
        qrel[((size_t)bh * 1024 + q0 + qq) * NREL + r] = s;
    }
}

// ---------------- fused flash attention with relative positions ---------------
// One block = (bh, 128-row q tile). 8 warps, each owns 16 q rows.
// Inputs q/k/v pre-rounded to tf32 bit patterns -> mma consumes raw bits.
// Output o stored bf16 (feeds Wo bgemm only).
#define FO_Q    0
#define FO_P    8704
#define FO_K    17408
#define FO_V    26112
#define FO_QREL 35328
#define FO_RELV 48640
#define FO_END  55508          // * 4 = 222032 bytes

__global__ void __launch_bounds__(256, 1)
flash_kernel(const float* __restrict__ q, const float* __restrict__ k,
             const float* __restrict__ v, const float* __restrict__ qrel,
             const float* __restrict__ relv, __nv_bfloat16* __restrict__ o) {
    extern __shared__ uint32_t fsm[];
    uint32_t* sQ = fsm + FO_Q;
    uint32_t* sP = fsm + FO_P;
    float* sQrel = (float*)(fsm + FO_QREL);
    float* sRelv = (float*)(fsm + FO_RELV);
    int bh = blockIdx.y;
    int b = bh >> 4, h = bh & 15;
    int q0 = blockIdx.x * 128;
    int tid = threadIdx.x, warp = tid >> 5, lane = tid & 31;
    int r = lane >> 2, cq = lane & 3;
    int wq = warp * 16;                      // warp's local q base

    const float* Qg = q + ((size_t)(b << 10) + q0) * 1024 + h * 64;
    const float* Kg = k + ((size_t)(b << 10)) * 1024 + h * 64;
    const float* Vg = v + ((size_t)(b << 10)) * 1024 + h * 64;
    uint32_t sbase = (uint32_t)__cvta_generic_to_shared(fsm);

    // coop loads: Q tile (already tf32 bits), qrel tile, rel_v table
    for (int i = tid; i < 2048; i += 256) {              // 128 rows x 16 f4
        int row = i >> 4, cg = (i & 15) * 4;
        float4 t = *(const float4*)&Qg[(size_t)row * 1024 + cg];
        sQ[row * 68 + cg + 0] = __float_as_uint(t.x);
        sQ[row * 68 + cg + 1] = __float_as_uint(t.y);
        sQ[row * 68 + cg + 2] = __float_as_uint(t.z);
        sQ[row * 68 + cg + 3] = __float_as_uint(t.w);
    }
    {
        const float* QR = qrel + ((size_t)bh * 1024 + q0) * NREL;
        for (int i = tid; i < 128 * NREL; i += 256)
            sQrel[(i / NREL) * 104 + (i % NREL)] = QR[i];
        for (int i = tid; i < NREL * 64; i += 256)
            sRelv[(i >> 6) * 68 + (i & 63)] = relv[i];
    }

    // K/V tile prefetch: 1024 16B-chunks per array; 4 per thread per array
    #define FL_PF(kt) do {                                                   \
        int buf_ = (kt) & 1;                                                 \
        uint32_t kb_ = sbase + (FO_K + buf_ * 4352) * 4;                     \
        uint32_t vb_ = sbase + (FO_V + buf_ * 4608) * 4;                     \
        const float* Ks_ = Kg + (size_t)((kt) * 64) * 1024;                  \
        const float* Vs_ = Vg + (size_t)((kt) * 64) * 1024;                  \
        _Pragma("unroll")                                                    \
        for (int i_ = 0; i_ < 4; i_++) {                                     \
            int c_ = tid + 256 * i_;                                         \
            int row_ = c_ >> 4, cg_ = (c_ & 15) * 4;                         \
            cpa16(kb_ + (row_ * 68 + cg_) * 4, Ks_ + (size_t)row_ * 1024 + cg_); \
            cpa16(vb_ + (row_ * 72 + cg_) * 4, Vs_ + (size_t)row_ * 1024 + cg_); \
        }                                                                    \
        cpa_commit();                                                        \
    } while (0)

    FL_PF(0);

    float m0_ = -1e30f, m1_ = -1e30f;
    float l0 = 0.f, l1 = 0.f, R0 = 0.f, R1 = 0.f, bs0 = 0.f, bs1 = 0.f;
    float O[8][4] = {};

    for (int kt = 0; kt < 16; kt++) {
        cpa_wait<0>();
        __syncthreads();
        if (kt + 1 < 16) FL_PF(kt + 1);
        const uint32_t* sKc = fsm + FO_K + (kt & 1) * 4352;
        const uint32_t* sVc = fsm + FO_V + (kt & 1) * 4608;
        int k0g = kt * 64;

        // ---- S = Q @ K^T ----
        float sc[8][4] = {};
        #pragma unroll
        for (int kk = 0; kk < 64; kk += 8) {
            uint32_t af[4];
            af[0] = sQ[(wq + r) * 68 + kk + cq];
            af[1] = sQ[(wq + r + 8) * 68 + kk + cq];
            af[2] = sQ[(wq + r) * 68 + kk + cq + 4];
            af[3] = sQ[(wq + r + 8) * 68 + kk + cq + 4];
            #pragma unroll
            for (int j = 0; j < 8; j++) {
                uint32_t bf[2];
                bf[0] = sKc[(8 * j + r) * 68 + kk + cq];
                bf[1] = sKc[(8 * j + r) * 68 + kk + cq + 4];
                mma8(sc[j], af, bf);
            }
        }
        // ---- bias + scale ----
        int row0 = q0 + wq + r, row1 = row0 + 8;
        #pragma unroll
        for (int j = 0; j < 8; j++) {
            #pragma unroll
            for (int e = 0; e < 4; e++) {
                int row_abs = (e < 2) ? row0 : row1;
                int rowl = (e < 2) ? (wq + r) : (wq + r + 8);
                int col_abs = k0g + 8 * j + 2 * cq + (e & 1);
                int d = min(max(col_abs - row_abs, -50), 50) + 50;
                sc[j][e] = (sc[j][e] + sQrel[rowl * 104 + d]) * 0.125f;
            }
        }
        // ---- online softmax stats ----
        float tm0 = -1e30f, tm1 = -1e30f;
        #pragma unroll
        for (int j = 0; j < 8; j++) {
            tm0 = fmaxf(tm0, fmaxf(sc[j][0], sc[j][1]));
            tm1 = fmaxf(tm1, fmaxf(sc[j][2], sc[j][3]));
        }
        tm0 = fmaxf(tm0, __shfl_xor_sync(0xffffffffu, tm0, 1));
        tm0 = fmaxf(tm0, __shfl_xor_sync(0xffffffffu, tm0, 2));
        tm1 = fmaxf(tm1, __shfl_xor_sync(0xffffffffu, tm1, 1));
        tm1 = fmaxf(tm1, __shfl_xor_sync(0xffffffffu, tm1, 2));
        float mn0 = fmaxf(m0_, tm0), mn1 = fmaxf(m1_, tm1);
        float a0 = __expf(m0_ - mn0), a1 = __expf(m1_ - mn1);
        m0_ = mn0; m1_ = mn1;
        float ls0 = 0.f, ls1 = 0.f, rs0 = 0.f, rs1 = 0.f;
        #pragma unroll
        for (int j = 0; j < 8; j++) {
            #pragma unroll
            for (int e = 0; e < 4; e++) {
                int row_abs = (e < 2) ? row0 : row1;
                int col_abs = k0g + 8 * j + 2 * cq + (e & 1);
                float p = __expf(sc[j][e] - ((e < 2) ? mn0 : mn1));
                sc[j][e] = p;
                if (e < 2) { ls0 += p; if (col_abs - row_abs >= 50) rs0 += p; }
                else       { ls1 += p; if (col_abs - row_abs >= 50) rs1 += p; }
            }
        }
        l0 = l0 * a0 + ls0; l1 = l1 * a1 + ls1;
        R0 = R0 * a0 + rs0; R1 = R1 * a1 + rs1;
        bs0 *= a0; bs1 *= a1;
        #pragma unroll
        for (int j = 0; j < 8; j++) {
            O[j][0] *= a0; O[j][1] *= a0; O[j][2] *= a1; O[j][3] *= a1;
        }
        // ---- write p to sP (raw fp32 bits; mma truncates to tf32) ----
        #pragma unroll
        for (int j = 0; j < 8; j++) {
            sP[(wq + r) * 68 + 8 * j + 2 * cq]     = __float_as_uint(sc[j][0]);
            sP[(wq + r) * 68 + 8 * j + 2 * cq + 1] = __float_as_uint(sc[j][1]);
            sP[(wq + r + 8) * 68 + 8 * j + 2 * cq]     = __float_as_uint(sc[j][2]);
            sP[(wq + r + 8) * 68 + 8 * j + 2 * cq + 1] = __float_as_uint(sc[j][3]);
        }
        __syncwarp();
        // ---- near-diagonal band: O += p * rel_v[k-q+50] ----
        if (k0g <= q0 + wq + 15 + 49 && k0g + 63 >= q0 + wq - 49) {
            #pragma unroll
            for (int ph = 0; ph < 2; ph++) {
                int rowl = wq + r + ph * 8;
                int base = (q0 + rowl) - k0g;       // kloc where k == q
                int klo = max(0, base - 49), khi = min(63, base + 49);
                float bsl = 0.f;
                for (int kl = klo; kl <= khi; kl++) {
                    float pv = __uint_as_float(sP[rowl * 68 + kl]);
                    const float* rv = &sRelv[(kl - base + 50) * 68];
                    bsl += pv;
                    #pragma unroll
                    for (int j = 0; j < 8; j++) {
                        int c0 = 8 * j + 2 * cq;
                        O[j][ph * 2 + 0] += pv * rv[c0];
                        O[j][ph * 2 + 1] += pv * rv[c0 + 1];
                    }
                }
                if (ph == 0) bs0 += bsl; else bs1 += bsl;
            }
        }
        // ---- O += P @ V ----
        #pragma unroll
        for (int kk = 0; kk < 64; kk += 8) {
            uint32_t af[4];
            af[0] = sP[(wq + r) * 68 + kk + cq];
            af[1] = sP[(wq + r + 8) * 68 + kk + cq];
            af[2] = sP[(wq + r) * 68 + kk + cq + 4];
            af[3] = sP[(wq + r + 8) * 68 + kk + cq + 4];
            #pragma unroll
            for (int j = 0; j < 8; j++) {
                uint32_t bf[2];
                bf[0] = sVc[(kk + cq) * 72 + 8 * j + r];
                bf[1] = sVc[(kk + cq + 4) * 72 + 8 * j + r];
                mma8(O[j], af, bf);
            }
        }
    }
    // ---- finalize ----
    l0 += __shfl_xor_sync(0xffffffffu, l0, 1);
    l0 += __shfl_xor_sync(0xffffffffu, l0, 2);
    l1 += __shfl_xor_sync(0xffffffffu, l1, 1);
    l1 += __shfl_xor_sync(0xffffffffu, l1, 2);
    R0 += __shfl_xor_sync(0xffffffffu, R0, 1);
    R0 += __shfl_xor_sync(0xffffffffu, R0, 2);
    R1 += __shfl_xor_sync(0xffffffffu, R1, 1);
    R1 += __shfl_xor_sync(0xffffffffu, R1, 2);
    float L0 = l0 - R0 - bs0, L1 = l1 - R1 - bs1;
    float inv0 = 1.0f / l0, inv1 = 1.0f / l1;
    int rowA = q0 + wq + r, rowB = rowA + 8;
    __nv_bfloat16* oA = o + ((size_t)(b << 10) + rowA) * 1024 + h * 64;
    __nv_bfloat16* oB = o + ((size_t)(b << 10) + rowB) * 1024 + h * 64;
    #pragma unroll
    for (int j = 0; j < 8; j++) {
        int c0 = 8 * j + 2 * cq;
        float rv0a = sRelv[c0], rv0b = sRelv[c0 + 1];
        float rva = sRelv[100 * 68 + c0], rvb = sRelv[100 * 68 + c0 + 1];
        *(__nv_bfloat162*)&oA[c0] = __floats2bfloat162_rn(
            (O[j][0] + L0 * rv0a + R0 * rva) * inv0,
            (O[j][1] + L0 * rv0b + R0 * rvb) * inv0);
        *(__nv_bfloat162*)&oB[c0] = __floats2bfloat162_rn(
            (O[j][2] + L1 * rv0a + R1 * rva) * inv1,
            (O[j][3] + L1 * rv0b + R1 * rvb) * inv1);
    }
}

// ---------------- host launch -------------------------------------------------
extern "C" void kernel_launch(void* const* d_in, const int* in_sizes, int n_in,
                              void* d_out, int out_size) {
    const float* x     = (const float*)d_in[0];
    const float* Wq    = (const float*)d_in[1];
    const float* bq    = (const float*)d_in[2];
    const float* Wk    = (const float*)d_in[3];
    const float* bk    = (const float*)d_in[4];
    const float* Wv    = (const float*)d_in[5];
    const float* bv    = (const float*)d_in[6];
    const float* Wo    = (const float*)d_in[7];
    const float* bo    = (const float*)d_in[8];
    const float* rel_k = (const float*)d_in[9];
    const float* rel_v = (const float*)d_in[10];
    const float* ga    = (const float*)d_in[11];
    const float* gf    = (const float*)d_in[12];
    const float* W_in  = (const float*)d_in[13];
    const float* b_in  = (const float*)d_in[14];
    const float* W_out = (const float*)d_in[15];
    const float* b_out = (const float*)d_in[16];
    float* out = (float*)d_out;

    float *hn, *qb, *kb, *vb, *qr, *h2, *ffin, *gel;
    __nv_bfloat16 *hnbf, *obf, *wbf;
    cudaGetSymbolAddress((void**)&hn,   g_hn);
    cudaGetSymbolAddress((void**)&hnbf, g_hnbf);
    cudaGetSymbolAddress((void**)&qb,   g_q);
    cudaGetSymbolAddress((void**)&kb,   g_k);
    cudaGetSymbolAddress((void**)&vb,   g_v);
    cudaGetSymbolAddress((void**)&qr,   g_qrel);
    cudaGetSymbolAddress((void**)&obf,  g_obf);
    cudaGetSymbolAddress((void**)&h2,   g_h2);
    cudaGetSymbolAddress((void**)&ffin, g_ffin);
    cudaGetSymbolAddress((void**)&gel,  g_gelu);
    cudaGetSymbolAddress((void**)&wbf,  g_wbf);

    const int FL_SMEM = FO_END * 4;                // 222032 B
    cudaFuncSetAttribute((const void*)tgemm_kernel<1,1>, cudaFuncAttributeMaxDynamicSharedMemorySize, TG_SMEM);
    cudaFuncSetAttribute((const void*)tgemm_kernel<3,0>, cudaFuncAttributeMaxDynamicSharedMemorySize, TG_SMEM);
    cudaFuncSetAttribute((const void*)bgemm_kernel<0>,   cudaFuncAttributeMaxDynamicSharedMemorySize, TG_SMEM);
    cudaFuncSetAttribute((const void*)bgemm_kernel<2>,   cudaFuncAttributeMaxDynamicSharedMemorySize, TG_SMEM);
    cudaFuncSetAttribute((const void*)flash_kernel, cudaFuncAttributeMaxDynamicSharedMemorySize, FL_SMEM);

    // 0. pre-round attention weights to bf16
    const int N1M4 = (1024 * 1024) / 4;
    round_bf16_kernel<<<N1M4 / 256, 256>>>((const float4*)Wq, wbf + WOFF_Q, N1M4);
    round_bf16_kernel<<<N1M4 / 256, 256>>>((const float4*)Wk, wbf + WOFF_K, N1M4);
    round_bf16_kernel<<<N1M4 / 256, 256>>>((const float4*)Wv, wbf + WOFF_V, N1M4);
    round_bf16_kernel<<<N1M4 / 256, 256>>>((const float4*)Wo, wbf + WOFF_O, N1M4);

    // 1. h = rmsnorm(x, g_attn) -> hn (full fp32) + hnbf (bf16), [S,B,D]->[B,S,D]
    rmsnorm_kernel<<<M4, 256>>>(x, ga, hn, nullptr, hnbf, 1);
    // 2. q, k, v  (bf16 GEMMs; outputs tf32-rounded fp32 for flash)
    dim3 g1(DMODEL / 128, M4 / 128);
    bgemm_kernel<0><<<g1, 256, TG_SMEM>>>(hnbf, wbf + WOFF_Q, bq, nullptr, qb, M4, DMODEL, DMODEL);
    bgemm_kernel<0><<<g1, 256, TG_SMEM>>>(hnbf, wbf + WOFF_K, bk, nullptr, kb, M4, DMODEL, DMODEL);
    bgemm_kernel<0><<<g1, 256, TG_SMEM>>>(hnbf, wbf + WOFF_V, bv, nullptr, vb, M4, DMODEL, DMODEL);
    // 3. qrel
    qrel_kernel<<<dim3(16, 64), 256>>>(qb, rel_k, qr);
    // 4. fused flash attention (stores o as bf16)
    flash_kernel<<<dim3(8, 64), 256, FL_SMEM>>>(qb, kb, vb, qr, rel_v, obf);
    // 5. h2 = hn + o @ Wo^T + bo   (bf16 GEMM, full fp32 out)
    bgemm_kernel<2><<<g1, 256, TG_SMEM>>>(obf, wbf + WOFF_O, bo, hn, h2, M4, DMODEL, DMODEL);
    // 6. ffin = rmsnorm(h2, g_ff)  (tf32-rounded only)
    rmsnorm_kernel<<<M4, 256>>>(h2, gf, nullptr, ffin, nullptr, 0);
    // 7. gelu(ffin @ W_in^T + b_in) (tf32 GEMM, tf32-rounded)
    tgemm_kernel<1,1><<<dim3(DFF / 128, M4 / 128), 256, TG_SMEM>>>(ffin, W_in, b_in, nullptr,
                                                                   gel, M4, DFF, DMODEL);
    // 8. out = h2 + gel @ W_out^T + b_out  (tf32 GEMM, full fp32, [S,B,D] order)
    tgemm_kernel<3,0><<<g1, 256, TG_SMEM>>>(gel, W_out, b_out, h2, out, M4, DMODEL, DFF);
}

// round 16
// speedup vs baseline: 1.1756x; 1.0100x over previous
#include <cuda_runtime.h>
#include <cuda_bf16.h>
#include <math.h>
#include <stdint.h>

// Problem constants
#define S_LEN 1024
#define BATCH 4
#define DMODEL 1024
#define NHEAD 16
#define HDIM 64
#define M4 4096          // BATCH * S_LEN
#define DFF 4096
#define NREL 101         // 2*MAXREL+1

// ---------------- scratch (device globals; no allocations allowed) ----------
__device__ float g_hn  [M4 * DMODEL];          // rmsnorm(x), full fp32 (residual)
__device__ __nv_bfloat16 g_hnbf[M4 * DMODEL];  // rmsnorm(x), bf16 (QKV GEMM A)
__device__ float g_q   [M4 * DMODEL];          // tf32-rounded
__device__ float g_k   [M4 * DMODEL];          // tf32-rounded
__device__ float g_v   [M4 * DMODEL];          // tf32-rounded
__device__ float g_qrel[64 * 1024 * NREL];     // [bh, q, r]
__device__ __nv_bfloat16 g_obf[M4 * DMODEL];   // attn head outputs, bf16 (Wo A)
__device__ float g_h2  [M4 * DMODEL];          // h + attn_out, full fp32
__device__ float g_ffin[M4 * DMODEL];          // rmsnorm(h2), tf32-rounded
__device__ float g_gelu[(size_t)M4 * DFF];     // gelu(...), tf32-rounded
__device__ __nv_bfloat16 g_wbf[4 * 1024 * 1024]; // bf16 attention weights
#define WOFF_Q   0
#define WOFF_K   (1024*1024)
#define WOFF_V   (2*1024*1024)
#define WOFF_O   (3*1024*1024)

// ---------------- helpers ----------------------------------------------------
__device__ __forceinline__ float gelu_f(float x) {
    return 0.5f * x * (1.0f + erff(x * 0.70710678118654752f));
}

__device__ __forceinline__ uint32_t f2tf(float f) {
    uint32_t u;
    asm("cvt.rna.tf32.f32 %0, %1;" : "=r"(u) : "f"(f));
    return u;
}
__device__ __forceinline__ float rnd_tf(float f) {
    return __uint_as_float(f2tf(f));
}

// D = A(16x8, row) * B(8x8, col) + D   (tf32 inputs, f32 accum)
__device__ __forceinline__ void mma8(float* c, const uint32_t* a, const uint32_t* b) {
    asm volatile(
        "mma.sync.aligned.m16n8k8.row.col.f32.tf32.tf32.f32 "
        "{%0,%1,%2,%3}, {%4,%5,%6,%7}, {%8,%9}, {%0,%1,%2,%3};"
        : "+f"(c[0]), "+f"(c[1]), "+f"(c[2]), "+f"(c[3])
        : "r"(a[0]), "r"(a[1]), "r"(a[2]), "r"(a[3]), "r"(b[0]), "r"(b[1]));
}

// D = A(16x16, row) * B(16x8, col) + D   (bf16 inputs, f32 accum)
__device__ __forceinline__ void mma16b(float* c, const uint32_t* a, const uint32_t* b) {
    asm volatile(
        "mma.sync.aligned.m16n8k16.row.col.f32.bf16.bf16.f32 "
        "{%0,%1,%2,%3}, {%4,%5,%6,%7}, {%8,%9}, {%0,%1,%2,%3};"
        : "+f"(c[0]), "+f"(c[1]), "+f"(c[2]), "+f"(c[3])
        : "r"(a[0]), "r"(a[1]), "r"(a[2]), "r"(a[3]), "r"(b[0]), "r"(b[1]));
}

// ldmatrix x4 (b16 mode; also used over fp32 data for tf32 frags)
__device__ __forceinline__ void ldsm4(uint32_t& r0, uint32_t& r1,
                                      uint32_t& r2, uint32_t& r3, uint32_t addr) {
    asm volatile("ldmatrix.sync.aligned.m8n8.x4.shared.b16 {%0,%1,%2,%3}, [%4];"
                 : "=r"(r0), "=r"(r1), "=r"(r2), "=r"(r3) : "r"(addr));
}

__device__ __forceinline__ void cpa16(uint32_t smem, const void* gmem) {
    asm volatile("cp.async.cg.shared.global [%0], [%1], 16;\n"
                 :: "r"(smem), "l"(gmem));
}
__device__ __forceinline__ void cpa_commit() {
    asm volatile("cp.async.commit_group;\n");
}
template <int N>
__device__ __forceinline__ void cpa_wait() {
    asm volatile("cp.async.wait_group %0;\n" :: "n"(N));
}

// 256-thread block reduce (8 warps). domax: true -> max, false -> sum.
__device__ __forceinline__ float blk_reduce(float v, float* red, bool domax) {
    #pragma unroll
    for (int o = 16; o > 0; o >>= 1) {
        float u = __shfl_xor_sync(0xffffffffu, v, o);
        v = domax ? fmaxf(v, u) : (v + u);
    }
    __syncthreads();
    if ((threadIdx.x & 31) == 0) red[threadIdx.x >> 5] = v;
    __syncthreads();
    float t = red[0];
    #pragma unroll
    for (int i = 1; i < 8; i++) t = domax ? fmaxf(t, red[i]) : (t + red[i]);
    return t;
}

// ---------------- bf16 pre-rounding (attention weights) -----------------------
__global__ void __launch_bounds__(256)
round_bf16_kernel(const float4* __restrict__ in, __nv_bfloat16* __restrict__ out,
                  int n4) {
    int i = blockIdx.x * 256 + threadIdx.x;
    if (i < n4) {
        float4 v = in[i];
        __nv_bfloat162 lo = __floats2bfloat162_rn(v.x, v.y);
        __nv_bfloat162 hi = __floats2bfloat162_rn(v.z, v.w);
        *(__nv_bfloat162*)&out[(size_t)i * 4]     = lo;
        *(__nv_bfloat162*)&out[(size_t)i * 4 + 2] = hi;
    }
}

// ---------------- RMSNorm -----------------------------------------------------
// out_full: fp32 (residual); out_r: tf32-rounded fp32; out_bf: bf16. Any may be null.
__global__ void __launch_bounds__(256)
rmsnorm_kernel(const float* __restrict__ in, const float* __restrict__ g,
               float* __restrict__ out_full, float* __restrict__ out_r,
               __nv_bfloat16* __restrict__ out_bf, int transpose_in) {
    __shared__ float red[8];
    int row = blockIdx.x;
    int tid = threadIdx.x;
    const float* xr = in + (size_t)row * DMODEL;
    float4 v = *(const float4*)&xr[tid * 4];
    float ss = v.x * v.x + v.y * v.y + v.z * v.z + v.w * v.w;
    ss = blk_reduce(ss, red, false);
    float rms = sqrtf(ss) * 0.03125f;                // /sqrt(1024)
    float inv = 1.0f / (rms + 1e-8f);
    float4 gv = *(const float4*)&g[tid * 4];
    float4 o = make_float4(v.x * inv * gv.x, v.y * inv * gv.y,
                           v.z * inv * gv.z, v.w * inv * gv.w);
    size_t orow = row;
    if (transpose_in) {
        int s = row >> 2, b = row & 3;               // row = s*B+b
        orow = ((size_t)b << 10) + s;                // out row = b*S+s
    }
    if (out_full)
        *(float4*)&out_full[orow * DMODEL + tid * 4] = o;
    if (out_r)
        *(float4*)&out_r[orow * DMODEL + tid * 4] =
            make_float4(rnd_tf(o.x), rnd_tf(o.y), rnd_tf(o.z), rnd_tf(o.w));
    if (out_bf) {
        *(__nv_bfloat162*)&out_bf[orow * DMODEL + tid * 4] =
            __floats2bfloat162_rn(o.x, o.y);
        *(__nv_bfloat162*)&out_bf[orow * DMODEL + tid * 4 + 2] =
            __floats2bfloat162_rn(o.z, o.w);
    }
}

// ---------------- tf32 tensor-core GEMM, KT=32, 3-stage cp.async + ldmatrix ---
#define TG_RS    36                   // row stride in u32 (32 + pad4)
#define TG_STAGE 4608                 // u32 per array per stage (128*36)
#define TG_BOFF  13824                // sB base offset in u32 (3 stages of A)
#define TG_SMEM  (2 * 13824 * 4)      // 110592 B
template <int EPI, int RND>
__global__ void __launch_bounds__(256, 2)
tgemm_kernel(const float* __restrict__ A, const float* __restrict__ W,
             const float* __restrict__ bias, const float* __restrict__ res,
             float* __restrict__ C, int M, int N, int K) {
    extern __shared__ uint32_t tsm[];
    int tid = threadIdx.x;
    int m0 = blockIdx.y * 128, n0 = blockIdx.x * 128;
    int warp = tid >> 5, lane = tid & 31;
    int wm = (warp & 1) * 64, wn = (warp >> 1) * 32;
    int r = lane >> 2, cq = lane & 3;
    int part = lane >> 3, lr = lane & 7;
    int aoff = (wm + (part & 1) * 8 + lr) * TG_RS + (part >> 1) * 4;
    int boff = (wn + (part >> 1) * 8 + lr) * TG_RS + (part & 1) * 4;

    int ar0 = tid >> 3, ak0 = (tid & 7) * 4;       // rows ar0 + 32*i, i=0..3
    const float* Ag[4];
    const float* Wg[4];
    uint32_t oa[4], ob[4];
    uint32_t sbase = (uint32_t)__cvta_generic_to_shared(tsm);
    #pragma unroll
    for (int i = 0; i < 4; i++) {
        int rw = ar0 + 32 * i;
        Ag[i] = A + (size_t)(m0 + rw) * K + ak0;
        Wg[i] = W + (size_t)(n0 + rw) * K + ak0;
        oa[i] = sbase + (rw * TG_RS + ak0) * 4;
        ob[i] = sbase + (TG_BOFF + rw * TG_RS + ak0) * 4;
    }

    float acc[4][4][4] = {};
    int T = K >> 5;

    #define TG_PF(g) do {                                   \
        int st_ = (g) % 3; int kof_ = (g) << 5;             \
        uint32_t sof_ = st_ * (TG_STAGE * 4);               \
        _Pragma("unroll")                                   \
        for (int i_ = 0; i_ < 4; i_++) {                    \
            cpa16(oa[i_] + sof_, Ag[i_] + kof_);            \
            cpa16(ob[i_] + sof_, Wg[i_] + kof_);            \
        }                                                   \
        cpa_commit();                                       \
    } while (0)

    TG_PF(0); TG_PF(1);

    for (int t = 0; t < T; t++) {
        if (t + 1 < T) cpa_wait<1>();
        else cpa_wait<0>();
        __syncthreads();
        uint32_t aS = sbase + ((t % 3) * TG_STAGE) * 4;
        uint32_t bS = sbase + ((TG_BOFF + (t % 3) * TG_STAGE)) * 4;
        #pragma unroll
        for (int kk = 0; kk < 32; kk += 8) {
            uint32_t af[4][4], bf[4][2];
            #pragma unroll
            for (int i = 0; i < 4; i++)
                ldsm4(af[i][0], af[i][1], af[i][2], af[i][3],
                      aS + (uint32_t)(aoff + i * (16 * TG_RS) + kk) * 4);
            #pragma unroll
            for (int jp = 0; jp < 2; jp++)
                ldsm4(bf[2 * jp][0], bf[2 * jp][1],
                      bf[2 * jp + 1][0], bf[2 * jp + 1][1],
                      bS + (uint32_t)(boff + jp * (16 * TG_RS) + kk) * 4);
            #pragma unroll
            for (int i = 0; i < 4; i++)
                #pragma unroll
                for (int j = 0; j < 4; j++)
                    mma8(acc[i][j], af[i], bf[j]);
        }
        if (t + 2 < T) TG_PF(t + 2);
    }
    float2 bb[4];
    #pragma unroll
    for (int j = 0; j < 4; j++)
        bb[j] = *(const float2*)&bias[n0 + wn + j * 8 + 2 * cq];
    #pragma unroll
    for (int i = 0; i < 4; i++)
        #pragma unroll
        for (int ph = 0; ph < 2; ph++) {
            int m = m0 + wm + i * 16 + r + ph * 8;
            #pragma unroll
            for (int j = 0; j < 4; j++) {
                int col = n0 + wn + j * 8 + 2 * cq;
                float v0 = acc[i][j][ph * 2 + 0] + bb[j].x;
                float v1 = acc[i][j][ph * 2 + 1] + bb[j].y;
                if (EPI == 1) { v0 = gelu_f(v0); v1 = gelu_f(v1); }
                if (EPI == 2 || EPI == 3) {
                    float2 rr = *(const float2*)&res[(size_t)m * 1024 + col];
                    v0 += rr.x; v1 += rr.y;
                }
                if (RND) { v0 = rnd_tf(v0); v1 = rnd_tf(v1); }
                size_t obp;
                if (EPI == 3) {
                    int b = m >> 10, s = m & 1023;
                    obp = ((size_t)(s * BATCH + b)) * DMODEL + col;
                } else {
                    obp = (size_t)m * N + col;
                }
                *(float2*)&C[obp] = make_float2(v0, v1);
            }
        }
}

// ---------------- bf16 tensor-core GEMM, KT=64, 3-stage cp.async + ldmatrix ---
#define BG_RS    72                   // row stride in halves (64 + pad8) = 144B
template <int EPI>
__global__ void __launch_bounds__(256, 2)
bgemm_kernel(const __nv_bfloat16* __restrict__ A,
             const __nv_bfloat16* __restrict__ W,
             const float* __restrict__ bias, const float* __restrict__ res,
             float* __restrict__ C, int M, int N, int K) {
    extern __shared__ uint32_t tsm[];
    int tid = threadIdx.x;
    int m0 = blockIdx.y * 128, n0 = blockIdx.x * 128;
    int warp = tid >> 5, lane = tid & 31;
    int wm = (warp & 1) * 64, wn = (warp >> 1) * 32;
    int r = lane >> 2, cq = lane & 3;
    int part = lane >> 3, lr = lane & 7;
    int aoffB = (wm + (part & 1) * 8 + lr) * 144 + (part >> 1) * 16;
    int boffB = (wn + (part >> 1) * 8 + lr) * 144 + (part & 1) * 16;

    int ar0 = tid >> 3, akh = (tid & 7) * 8;       // halves
    const __nv_bfloat16* Ag[4];
    const __nv_bfloat16* Wg[4];
    uint32_t oa[4], ob[4];
    uint32_t sbase = (uint32_t)__cvta_generic_to_shared(tsm);
    #pragma unroll
    for (int i = 0; i < 4; i++) {
        int rw = ar0 + 32 * i;
        Ag[i] = A + (size_t)(m0 + rw) * K + akh;
        Wg[i] = W + (size_t)(n0 + rw) * K + akh;
        oa[i] = sbase + rw * 144 + akh * 2;
        ob[i] = sbase + TG_BOFF * 4 + rw * 144 + akh * 2;
    }

    float acc[4][4][4] = {};
    int T = K >> 6;                    // KT = 64 halves

    #define BG_PF(g) do {                                   \
        int st_ = (g) % 3; int kof_ = (g) << 6;             \
        uint32_t sof_ = st_ * (TG_STAGE * 4);               \
        _Pragma("unroll")                                   \
        for (int i_ = 0; i_ < 4; i_++) {                    \
            cpa16(oa[i_] + sof_, Ag[i_] + kof_);            \
            cpa16(ob[i_] + sof_, Wg[i_] + kof_);            \
        }                                                   \
        cpa_commit();                                       \
    } while (0)

    BG_PF(0); BG_PF(1);                // K >= 128 always

    for (int t = 0; t < T; t++) {
        if (t + 1 < T) cpa_wait<1>();
        else cpa_wait<0>();
        __syncthreads();
        uint32_t aS = sbase + ((t % 3) * TG_STAGE) * 4;
        uint32_t bS = sbase + ((TG_BOFF + (t % 3) * TG_STAGE)) * 4;
        #pragma unroll
        for (int kk = 0; kk < 64; kk += 16) {     // 4 k16 steps
            uint32_t af[4][4], bf[4][2];
            #pragma unroll
            for (int i = 0; i < 4; i++)
                ldsm4(af[i][0], af[i][1], af[i][2], af[i][3],
                      aS + (uint32_t)(aoffB + i * (16 * 144) + kk * 2));
            #pragma unroll
            for (int jp = 0; jp < 2; jp++)
                ldsm4(bf[2 * jp][0], bf[2 * jp][1],
                      bf[2 * jp + 1][0], bf[2 * jp + 1][1],
                      bS + (uint32_t)(boffB + jp * (16 * 144) + kk * 2));
            #pragma unroll
            for (int i = 0; i < 4; i++)
                #pragma unroll
                for (int j = 0; j < 4; j++)
                    mma16b(acc[i][j], af[i], bf[j]);
        }
        if (t + 2 < T) BG_PF(t + 2);
    }
    float2 bb[4];
    #pragma unroll
    for (int j = 0; j < 4; j++)
        bb[j] = *(const float2*)&bias[n0 + wn + j * 8 + 2 * cq];
    #pragma unroll
    for (int i = 0; i < 4; i++)
        #pragma unroll
        for (int ph = 0; ph < 2; ph++) {
            int m = m0 + wm + i * 16 + r + ph * 8;
            #pragma unroll
            for (int j = 0; j < 4; j++) {
                int col = n0 + wn + j * 8 + 2 * cq;
                float v0 = acc[i][j][ph * 2 + 0] + bb[j].x;
                float v1 = acc[i][j][ph * 2 + 1] + bb[j].y;
                if (EPI == 2) {
                    float2 rr = *(const float2*)&res[(size_t)m * 1024 + col];
                    v0 += rr.x; v1 += rr.y;
                } else {
                    v0 = rnd_tf(v0); v1 = rnd_tf(v1);
                }
                *(float2*)&C[(size_t)m * N + col] = make_float2(v0, v1);
            }
        }
}

// ---------------- qrel: qrel[bh,q,r] = q_head[q,:] . rel_k[r,:] ---------------
__global__ void __launch_bounds__(256)
qrel_kernel(const float* __restrict__ q, const float* __restrict__ relk,
            float* __restrict__ qrel) {
    __shared__ float sR[NREL][65];
    __shared__ float sQ[64][65];
    int bh = blockIdx.y;
    int b = bh >> 4, h = bh & 15;
    int q0 = blockIdx.x * 64;
    int tid = threadIdx.x;
    const float* Q = q + ((size_t)(b * S_LEN) + q0) * DMODEL + h * HDIM;
    for (int i = tid; i < NREL * 64; i += 256) {
        int r = i >> 6, d = i & 63;
        sR[r][d] = relk[i];
    }
    for (int i = tid; i < 64 * 64; i += 256) {
        int r = i >> 6, d = i & 63;
        sQ[r][d] = Q[(size_t)r * DMODEL + d];
    }
    __syncthreads();
    for (int i = tid; i < 64 * NREL; i += 256) {
        int qq = i / NREL, r = i % NREL;
        float s = 0.f;
        #pragma unroll
        for (int d = 0; d < 64; d++) s += sQ[qq][d] * sR[r][d];
        qrel[((size_t)bh * 1024 + q0 + qq) * NREL + r] = s;
    }
}

// ---------------- fused flash attention with relative positions ---------------
// One block = (bh, 128-row q tile). 8 warps, each owns 16 q rows.
// Q fragments hoisted to registers; K and P fragments via ldmatrix (fp32-b16
// trick, same maps as tgemm); V stays scalar LDS (needs transposed access).
#define FO_Q    0
#define FO_P    8704
#define FO_K    17408
#define FO_V    26112
#define FO_QREL 35328
#define FO_RELV 48640
#define FO_END  55508          // * 4 = 222032 bytes

__global__ void __launch_bounds__(256, 1)
flash_kernel(const float* __restrict__ q, const float* __restrict__ k,
             const float* __restrict__ v, const float* __restrict__ qrel,
             const float* __restrict__ relv, __nv_bfloat16* __restrict__ o) {
    extern __shared__ uint32_t fsm[];
    uint32_t* sQ = fsm + FO_Q;
    uint32_t* sP = fsm + FO_P;
    float* sQrel = (float*)(fsm + FO_QREL);
    float* sRelv = (float*)(fsm + FO_RELV);
    int bh = blockIdx.y;
    int b = bh >> 4, h = bh & 15;
    int q0 = blockIdx.x * 128;
    int tid = threadIdx.x, warp = tid >> 5, lane = tid & 31;
    int r = lane >> 2, cq = lane & 3;
    int part = lane >> 3, lr = lane & 7;
    int wq = warp * 16;                      // warp's local q base

    const float* Qg = q + ((size_t)(b << 10) + q0) * 1024 + h * 64;
    const float* Kg = k + ((size_t)(b << 10)) * 1024 + h * 64;
    const float* Vg = v + ((size_t)(b << 10)) * 1024 + h * 64;
    uint32_t sbase = (uint32_t)__cvta_generic_to_shared(fsm);

    // ldmatrix offsets (u32 units):
    // A-pattern (Q from sQ, P from sP): rows wq + (part&1)*8 + lr, kcol (part>>1)*4
    //   -> m0=(rows wq..+7 @kk) m1=(+8 @kk) m2=(wq..+7 @kk+4) m3=(+8 @kk+4)
    //   matches a0=(r,cq) a1=(r+8,cq) a2=(r,cq+4) a3=(r+8,cq+4)
    int aoffQP = ((part & 1) * 8 + lr) * 68 + (part >> 1) * 4;
    // B-pattern (K from sKc): rows (part>>1)*8 + lr, kcol (part&1)*4
    //   one ldsm4 covers j-groups {2jp, 2jp+1}: m0=(j2jp,@kk) m1=(j2jp,@kk+4)
    //   m2=(j2jp+1,@kk) m3=(j2jp+1,@kk+4); jp stride = 16 rows
    int boffK = ((part >> 1) * 8 + lr) * 68 + (part & 1) * 4;

    // coop loads: Q tile (already tf32 bits), qrel tile, rel_v table
    for (int i = tid; i < 2048; i += 256) {              // 128 rows x 16 f4
        int row = i >> 4, cg = (i & 15) * 4;
        float4 t = *(const float4*)&Qg[(size_t)row * 1024 + cg];
        sQ[row * 68 + cg + 0] = __float_as_uint(t.x);
        sQ[row * 68 + cg + 1] = __float_as_uint(t.y);
        sQ[row * 68 + cg + 2] = __float_as_uint(t.z);
        sQ[row * 68 + cg + 3] = __float_as_uint(t.w);
    }
    {
        const float* QR = qrel + ((size_t)bh * 1024 + q0) * NREL;
        for (int i = tid; i < 128 * NREL; i += 256)
            sQrel[(i / NREL) * 104 + (i % NREL)] = QR[i];
        for (int i = tid; i < NREL * 64; i += 256)
            sRelv[(i >> 6) * 68 + (i & 63)] = relv[i];
    }

    // K/V tile prefetch: 1024 16B-chunks per array; 4 per thread per array
    #define FL_PF(kt) do {                                                   \
        int buf_ = (kt) & 1;                                                 \
        uint32_t kb_ = sbase + (FO_K + buf_ * 4352) * 4;                     \
        uint32_t vb_ = sbase + (FO_V + buf_ * 4608) * 4;                     \
        const float* Ks_ = Kg + (size_t)((kt) * 64) * 1024;                  \
        const float* Vs_ = Vg + (size_t)((kt) * 64) * 1024;                  \
        _Pragma("unroll")                                                    \
        for (int i_ = 0; i_ < 4; i_++) {                                     \
            int c_ = tid + 256 * i_;                                         \
            int row_ = c_ >> 4, cg_ = (c_ & 15) * 4;                         \
            cpa16(kb_ + (row_ * 68 + cg_) * 4, Ks_ + (size_t)row_ * 1024 + cg_); \
            cpa16(vb_ + (row_ * 72 + cg_) * 4, Vs_ + (size_t)row_ * 1024 + cg_); \
        }                                                                    \
        cpa_commit();                                                        \
    } while (0)

    FL_PF(0);
    __syncthreads();                   // sQ visible for fragment hoist

    // Hoist Q fragments: qf[kk8] covers k = 8*kk8 .. +7 for this warp's 16 rows
    uint32_t qf[8][4];
    uint32_t qAddrBase = sbase + (uint32_t)(FO_Q + wq * 68 + aoffQP) * 4;
    #pragma unroll
    for (int kk8 = 0; kk8 < 8; kk8++)
        ldsm4(qf[kk8][0], qf[kk8][1], qf[kk8][2], qf[kk8][3],
              qAddrBase + (uint32_t)(kk8 * 8) * 4);

    uint32_t pAddrBase = sbase + (uint32_t)(FO_P + wq * 68 + aoffQP) * 4;

    float m0_ = -1e30f, m1_ = -1e30f;
    float l0 = 0.f, l1 = 0.f, R0 = 0.f, R1 = 0.f, bs0 = 0.f, bs1 = 0.f;
    float O[8][4] = {};

    for (int kt = 0; kt < 16; kt++) {
        cpa_wait<0>();
        __syncthreads();
        if (kt + 1 < 16) FL_PF(kt + 1);
        const uint32_t* sVc = fsm + FO_V + (kt & 1) * 4608;
        uint32_t kAddrBase = sbase + (uint32_t)(FO_K + (kt & 1) * 4352 + boffK) * 4;
        int k0g = kt * 64;

        // ---- S = Q @ K^T  (ldsm fragments) ----
        float sc[8][4] = {};
        #pragma unroll
        for (int kk8 = 0; kk8 < 8; kk8++) {
            uint32_t bfk[8][2];
            #pragma unroll
            for (int jp = 0; jp < 4; jp++)
                ldsm4(bfk[2 * jp][0], bfk[2 * jp][1],
                      bfk[2 * jp + 1][0], bfk[2 * jp + 1][1],
                      kAddrBase + (uint32_t)(jp * (16 * 68) + kk8 * 8) * 4);
            #pragma unroll
            for (int j = 0; j < 8; j++)
                mma8(sc[j], qf[kk8], bfk[j]);
        }
        // ---- bias + scale ----
        int row0 = q0 + wq + r, row1 = row0 + 8;
        #pragma unroll
        for (int j = 0; j < 8; j++) {
            #pragma unroll
            for (int e = 0; e < 4; e++) {
                int row_abs = (e < 2) ? row0 : row1;
                int rowl = (e < 2) ? (wq + r) : (wq + r + 8);
                int col_abs = k0g + 8 * j + 2 * cq + (e & 1);
                int d = min(max(col_abs - row_abs, -50), 50) + 50;
                sc[j][e] = (sc[j][e] + sQrel[rowl * 104 + d]) * 0.125f;
            }
        }
        // ---- online softmax stats ----
        float tm0 = -1e30f, tm1 = -1e30f;
        #pragma unroll
        for (int j = 0; j < 8; j++) {
            tm0 = fmaxf(tm0, fmaxf(sc[j][0], sc[j][1]));
            tm1 = fmaxf(tm1, fmaxf(sc[j][2], sc[j][3]));
        }
        tm0 = fmaxf(tm0, __shfl_xor_sync(0xffffffffu, tm0, 1));
        tm0 = fmaxf(tm0, __shfl_xor_sync(0xffffffffu, tm0, 2));
        tm1 = fmaxf(tm1, __shfl_xor_sync(0xffffffffu, tm1, 1));
        tm1 = fmaxf(tm1, __shfl_xor_sync(0xffffffffu, tm1, 2));
        float mn0 = fmaxf(m0_, tm0), mn1 = fmaxf(m1_, tm1);
        float a0 = __expf(m0_ - mn0), a1 = __expf(m1_ - mn1);
        m0_ = mn0; m1_ = mn1;
        float ls0 = 0.f, ls1 = 0.f, rs0 = 0.f, rs1 = 0.f;
        #pragma unroll
        for (int j = 0; j < 8; j++) {
            #pragma unroll
            for (int e = 0; e < 4; e++) {
                int row_abs = (e < 2) ? row0 : row1;
                int col_abs = k0g + 8 * j + 2 * cq + (e & 1);
                float p = __expf(sc[j][e] - ((e < 2) ? mn0 : mn1));
                sc[j][e] = p;
                if (e < 2) { ls0 += p; if (col_abs - row_abs >= 50) rs0 += p; }
                else       { ls1 += p; if (col_abs - row_abs >= 50) rs1 += p; }
            }
        }
        l0 = l0 * a0 + ls0; l1 = l1 * a1 + ls1;
        R0 = R0 * a0 + rs0; R1 = R1 * a1 + rs1;
        bs0 *= a0; bs1 *= a1;
        #pragma unroll
        for (int j = 0; j < 8; j++) {
            O[j][0] *= a0; O[j][1] *= a0; O[j][2] *= a1; O[j][3] *= a1;
        }
        // ---- write p to sP (raw fp32 bits; mma truncates to tf32) ----
        #pragma unroll
        for (int j = 0; j < 8; j++) {
            sP[(wq + r) * 68 + 8 * j + 2 * cq]     = __float_as_uint(sc[j][0]);
            sP[(wq + r) * 68 + 8 * j + 2 * cq + 1] = __float_as_uint(sc[j][1]);
            sP[(wq + r + 8) * 68 + 8 * j + 2 * cq]     = __float_as_uint(sc[j][2]);
            sP[(wq + r + 8) * 68 + 8 * j + 2 * cq + 1] = __float_as_uint(sc[j][3]);
        }
        __syncwarp();
        // ---- near-diagonal band: O += p * rel_v[k-q+50] ----
        if (k0g <= q0 + wq + 15 + 49 && k0g + 63 >= q0 + wq - 49) {
            #pragma unroll
            for (int ph = 0; ph < 2; ph++) {
                int rowl = wq + r + ph * 8;
                int base = (q0 + rowl) - k0g;       // kloc where k == q
                int klo = max(0, base - 49), khi = min(63, base + 49);
                float bsl = 0.f;
                for (int kl = klo; kl <= khi; kl++) {
                    float pv = __uint_as_float(sP[rowl * 68 + kl]);
                    const float* rv = &sRelv[(kl - base + 50) * 68];
                    bsl += pv;
                    #pragma unroll
                    for (int j = 0; j < 8; j++) {
                        int c0 = 8 * j + 2 * cq;
                        O[j][ph * 2 + 0] += pv * rv[c0];
                        O[j][ph * 2 + 1] += pv * rv[c0 + 1];
                    }
                }
                if (ph == 0) bs0 += bsl; else bs1 += bsl;
            }
        }
        // ---- O += P @ V  (P via ldsm; V scalar, transposed access) ----
        #pragma unroll
        for (int kk8 = 0; kk8 < 8; kk8++) {
            int kk = kk8 * 8;
            uint32_t pf[4];
            ldsm4(pf[0], pf[1], pf[2], pf[3],
                  pAddrBase + (uint32_t)kk * 4);
            #pragma unroll
            for (int j = 0; j < 8; j++) {
                uint32_t bf[2];
                bf[0] = sVc[(kk + cq) * 72 + 8 * j + r];
                bf[1] = sVc[(kk + cq + 4) * 72 + 8 * j + r];
                mma8(O[j], pf, bf);
            }
        }
    }
    // ---- finalize ----
    l0 += __shfl_xor_sync(0xffffffffu, l0, 1);
    l0 += __shfl_xor_sync(0xffffffffu, l0, 2);
    l1 += __shfl_xor_sync(0xffffffffu, l1, 1);
    l1 += __shfl_xor_sync(0xffffffffu, l1, 2);
    R0 += __shfl_xor_sync(0xffffffffu, R0, 1);
    R0 += __shfl_xor_sync(0xffffffffu, R0, 2);
    R1 += __shfl_xor_sync(0xffffffffu, R1, 1);
    R1 += __shfl_xor_sync(0xffffffffu, R1, 2);
    float L0 = l0 - R0 - bs0, L1 = l1 - R1 - bs1;
    float inv0 = 1.0f / l0, inv1 = 1.0f / l1;
    int rowA = q0 + wq + r, rowB = rowA + 8;
    __nv_bfloat16* oA = o + ((size_t)(b << 10) + rowA) * 1024 + h * 64;
    __nv_bfloat16* oB = o + ((size_t)(b << 10) + rowB) * 1024 + h * 64;
    #pragma unroll
    for (int j = 0; j < 8; j++) {
        int c0 = 8 * j + 2 * cq;
        float rv0a = sRelv[c0], rv0b = sRelv[c0 + 1];
        float rva = sRelv[100 * 68 + c0], rvb = sRelv[100 * 68 + c0 + 1];
        *(__nv_bfloat162*)&oA[c0] = __floats2bfloat162_rn(
            (O[j][0] + L0 * rv0a + R0 * rva) * inv0,
            (O[j][1] + L0 * rv0b + R0 * rvb) * inv0);
        *(__nv_bfloat162*)&oB[c0] = __floats2bfloat162_rn(
            (O[j][2] + L1 * rv0a + R1 * rva) * inv1,
            (O[j][3] + L1 * rv0b + R1 * rvb) * inv1);
    }
}

// ---------------- host launch -------------------------------------------------
extern "C" void kernel_launch(void* const* d_in, const int* in_sizes, int n_in,
                              void* d_out, int out_size) {
    const float* x     = (const float*)d_in[0];
    const float* Wq    = (const float*)d_in[1];
    const float* bq    = (const float*)d_in[2];
    const float* Wk    = (const float*)d_in[3];
    const float* bk    = (const float*)d_in[4];
    const float* Wv    = (const float*)d_in[5];
    const float* bv    = (const float*)d_in[6];
    const float* Wo    = (const float*)d_in[7];
    const float* bo    = (const float*)d_in[8];
    const float* rel_k = (const float*)d_in[9];
    const float* rel_v = (const float*)d_in[10];
    const float* ga    = (const float*)d_in[11];
    const float* gf    = (const float*)d_in[12];
    const float* W_in  = (const float*)d_in[13];
    const float* b_in  = (const float*)d_in[14];
    const float* W_out = (const float*)d_in[15];
    const float* b_out = (const float*)d_in[16];
    float* out = (float*)d_out;

    float *hn, *qb, *kb, *vb, *qr, *h2, *ffin, *gel;
    __nv_bfloat16 *hnbf, *obf, *wbf;
    cudaGetSymbolAddress((void**)&hn,   g_hn);
    cudaGetSymbolAddress((void**)&hnbf, g_hnbf);
    cudaGetSymbolAddress((void**)&qb,   g_q);
    cudaGetSymbolAddress((void**)&kb,   g_k);
    cudaGetSymbolAddress((void**)&vb,   g_v);
    cudaGetSymbolAddress((void**)&qr,   g_qrel);
    cudaGetSymbolAddress((void**)&obf,  g_obf);
    cudaGetSymbolAddress((void**)&h2,   g_h2);
    cudaGetSymbolAddress((void**)&ffin, g_ffin);
    cudaGetSymbolAddress((void**)&gel,  g_gelu);
    cudaGetSymbolAddress((void**)&wbf,  g_wbf);

    const int FL_SMEM = FO_END * 4;                // 222032 B
    cudaFuncSetAttribute((const void*)tgemm_kernel<1,1>, cudaFuncAttributeMaxDynamicSharedMemorySize, TG_SMEM);
    cudaFuncSetAttribute((const void*)tgemm_kernel<3,0>, cudaFuncAttributeMaxDynamicSharedMemorySize, TG_SMEM);
    cudaFuncSetAttribute((const void*)bgemm_kernel<0>,   cudaFuncAttributeMaxDynamicSharedMemorySize, TG_SMEM);
    cudaFuncSetAttribute((const void*)bgemm_kernel<2>,   cudaFuncAttributeMaxDynamicSharedMemorySize, TG_SMEM);
    cudaFuncSetAttribute((const void*)flash_kernel, cudaFuncAttributeMaxDynamicSharedMemorySize, FL_SMEM);

    // 0. pre-round attention weights to bf16
    const int N1M4 = (1024 * 1024) / 4;
    round_bf16_kernel<<<N1M4 / 256, 256>>>((const float4*)Wq, wbf + WOFF_Q, N1M4);
    round_bf16_kernel<<<N1M4 / 256, 256>>>((const float4*)Wk, wbf + WOFF_K, N1M4);
    round_bf16_kernel<<<N1M4 / 256, 256>>>((const float4*)Wv, wbf + WOFF_V, N1M4);
    round_bf16_kernel<<<N1M4 / 256, 256>>>((const float4*)Wo, wbf + WOFF_O, N1M4);

    // 1. h = rmsnorm(x, g_attn) -> hn (full fp32) + hnbf (bf16), [S,B,D]->[B,S,D]
    rmsnorm_kernel<<<M4, 256>>>(x, ga, hn, nullptr, hnbf, 1);
    // 2. q, k, v  (bf16 GEMMs; outputs tf32-rounded fp32 for flash)
    dim3 g1(DMODEL / 128, M4 / 128);
    bgemm_kernel<0><<<g1, 256, TG_SMEM>>>(hnbf, wbf + WOFF_Q, bq, nullptr, qb, M4, DMODEL, DMODEL);
    bgemm_kernel<0><<<g1, 256, TG_SMEM>>>(hnbf, wbf + WOFF_K, bk, nullptr, kb, M4, DMODEL, DMODEL);
    bgemm_kernel<0><<<g1, 256, TG_SMEM>>>(hnbf, wbf + WOFF_V, bv, nullptr, vb, M4, DMODEL, DMODEL);
    // 3. qrel
    qrel_kernel<<<dim3(16, 64), 256>>>(qb, rel_k, qr);
    // 4. fused flash attention (stores o as bf16)
    flash_kernel<<<dim3(8, 64), 256, FL_SMEM>>>(qb, kb, vb, qr, rel_v, obf);
    // 5. h2 = hn + o @ Wo^T + bo   (bf16 GEMM, full fp32 out)
    bgemm_kernel<2><<<g1, 256, TG_SMEM>>>(obf, wbf + WOFF_O, bo, hn, h2, M4, DMODEL, DMODEL);
    // 6. ffin = rmsnorm(h2, g_ff)  (tf32-rounded only)
    rmsnorm_kernel<<<M4, 256>>>(h2, gf, nullptr, ffin, nullptr, 0);
    // 7. gelu(ffin @ W_in^T + b_in) (tf32 GEMM, tf32-rounded)
    tgemm_kernel<1,1><<<dim3(DFF / 128, M4 / 128), 256, TG_SMEM>>>(ffin, W_in, b_in, nullptr,
                                                                   gel, M4, DFF, DMODEL);
    // 8. out = h2 + gel @ W_out^T + b_out  (tf32 GEMM, full fp32, [S,B,D] order)
    tgemm_kernel<3,0><<<g1, 256, TG_SMEM>>>(gel, W_out, b_out, h2, out, M4, DMODEL, DFF);
}